// round 6
// baseline (speedup 1.0000x reference)
#include <cuda_runtime.h>
#include <cuda_fp16.h>
#include <math.h>
#include <stdint.h>

#define Bb 8
#define Ss 1024
#define Dd 1024
#define Hh 16
#define HDIM 64
#define Ff 4096
#define Mm (Bb*Ss)

// ---------------------------------------------------------------------------
// Scratch (device globals). Pair tensors: [0..n) = hi plane, [n..2n) = lo.
// ---------------------------------------------------------------------------
__device__ __half g_qp [2*(size_t)Mm*Dd];
__device__ __half g_kp [2*(size_t)Mm*Dd];
__device__ __half g_vp [2*(size_t)Mm*Dd];
__device__ __half g_Qp [2*(size_t)Mm*Dd];
__device__ __half g_Kp [2*(size_t)Mm*Dd];
__device__ __half g_Vp [2*(size_t)Mm*Dd];
__device__ __half g_Vtp[2*(size_t)Bb*Hh*HDIM*Ss];
__device__ __half g_ctx[2*(size_t)Mm*Dd];
__device__ __half g_aop[2*(size_t)Mm*Dd];
__device__ __half g_Fp [2*(size_t)Mm*Ff];
__device__ __half g_Ph [(size_t)Bb*Hh*Ss*Ss];      // P: single fp16 plane
__device__ __half g_WTp[2*(size_t)(4*Dd*Dd + Dd*Ff + Ff*Dd)];
__device__ float  g_S  [(size_t)Bb*Hh*Ss*Ss];
__device__ float  g_X  [(size_t)Mm*Dd];
__device__ float  g_ao [(size_t)Mm*Dd];
__device__ float  g_Z  [(size_t)Mm*Dd];

// ---------------------------------------------------------------------------
// PTX helpers (baseline sm_80+ features, valid on plain sm_103 target)
// ---------------------------------------------------------------------------
__device__ __forceinline__ uint32_t smem_u32(const void* p) {
    uint32_t a;
    asm("{ .reg .u64 t; cvta.to.shared.u64 t, %1; cvt.u32.u64 %0, t; }"
        : "=r"(a) : "l"(p));
    return a;
}
__device__ __forceinline__ void ldsm4(uint32_t& r0, uint32_t& r1, uint32_t& r2,
                                      uint32_t& r3, uint32_t addr) {
    asm volatile("ldmatrix.sync.aligned.m8n8.x4.shared.b16 {%0,%1,%2,%3}, [%4];"
                 : "=r"(r0), "=r"(r1), "=r"(r2), "=r"(r3) : "r"(addr));
}
__device__ __forceinline__ void mma16816(float* d, const uint32_t* a,
                                         const uint32_t* b) {
    asm volatile(
        "mma.sync.aligned.m16n8k16.row.col.f32.f16.f16.f32 "
        "{%0,%1,%2,%3}, {%4,%5,%6,%7}, {%8,%9}, {%0,%1,%2,%3};"
        : "+f"(d[0]), "+f"(d[1]), "+f"(d[2]), "+f"(d[3])
        : "r"(a[0]), "r"(a[1]), "r"(a[2]), "r"(a[3]), "r"(b[0]), "r"(b[1]));
}
__device__ __forceinline__ void cpa16(uint32_t dst, const void* src) {
    asm volatile("cp.async.cg.shared.global [%0], [%1], 16;"
                 :: "r"(dst), "l"(src) : "memory");
}
#define CP_COMMIT() asm volatile("cp.async.commit_group;" ::: "memory")
#define CP_WAIT0()  asm volatile("cp.async.wait_group 0;" ::: "memory")

// fp32 pair split store: hi = f16(x), lo = f16(x - hi)
__device__ __forceinline__ void store_pair(__half* H, __half* L, size_t off,
                                           float2 v) {
    __half2 h = __floats2half2_rn(v.x, v.y);
    float2 hf = __half22float2(h);
    __half2 l = __floats2half2_rn(v.x - hf.x, v.y - hf.y);
    *(__half2*)(H + off) = h;
    *(__half2*)(L + off) = l;
}

// ---------------------------------------------------------------------------
// GEMM on fp16 operands via mma.sync, fp32-equivalent accuracy:
//   C[128 x BN] = A[128,K] @ B[BN,K]^T, fp32 accum.
//   AFMT=0: A is hi/lo pair -> D = Ah*Bh + Al*Bh + Ah*Bl  (3 MMAs)
//   AFMT=2: A is single fp16 -> D = A*Bh + A*Bl           (2 MMAs)
//   B always hi/lo pair. 2-stage cp.async pipeline.
//   Warp grid fixed 2(m) x 4(n): warp tile 64 x (BN/4).
//   BN=256 -> 64x64 warp tile (LDS-optimal), 1 CTA/SM.
//   Batch via blockIdx.z: off = (z>>4)*s1 + (z&15)*s2 (elements per plane).
//   EPI: 0=+bias  1=+bias,relu  2=scores(x/8+(1-mask)*-1e4)  3=plain
//   CFMT: 0 = fp32 out (C) ; 1 = fp16 pair out (CH/CL)
// ---------------------------------------------------------------------------
template<int BN, int EPI, int CFMT, int AFMT>
__global__ void __launch_bounds__(256, (BN >= 256 ? 1 : 2)) gemm_ps(
    const __half* __restrict__ AH, const __half* __restrict__ AL,
    long long lda, long long a1, long long a2,
    const __half* __restrict__ BH, const __half* __restrict__ BL,
    long long ldb, long long b1, long long b2,
    float* __restrict__ C, __half* __restrict__ CH, __half* __restrict__ CL,
    long long ldc, long long c1, long long c2,
    const float* __restrict__ aux, int K)
{
    constexpr int MF = 4;                 // m16 frags per warp (m span 64)
    constexpr int NF = BN / 32;           // n8 frags per warp (n span BN/4)
    constexpr int NBI = BN / 64;          // B cp.async iters per plane
    constexpr int ABYTES = (AFMT == 0) ? 20480 : 10240;
    constexpr int STAGE = ABYTES + BN * 160;

    extern __shared__ char dsm[];

    const int tid = threadIdx.x, lane = tid & 31, wid = tid >> 5;
    const int zb = blockIdx.z >> 4, zh = blockIdx.z & 15;
    const int row0 = blockIdx.y * 128, col0 = blockIdx.x * BN;
    const int m0w = (wid >> 2) * 64, n0w = (wid & 3) * (BN / 4);

    const __half* Abh = AH + zb * a1 + zh * a2 + (size_t)row0 * lda;
    const __half* Abl = (AFMT == 0) ? (AL + zb * a1 + zh * a2 + (size_t)row0 * lda)
                                    : nullptr;
    const __half* Bbh = BH + zb * b1 + zh * b2 + (size_t)col0 * ldb;
    const __half* Bbl = BL + zb * b1 + zh * b2 + (size_t)col0 * ldb;
    float* Cb = C + zb * c1 + zh * c2;
    __half* CbH = CH + zb * c1 + zh * c2;
    __half* CbL = CL + zb * c1 + zh * c2;

    const uint32_t sbase = smem_u32(dsm);

    float acc[MF][NF][4];
#pragma unroll
    for (int i = 0; i < MF; i++)
#pragma unroll
        for (int j = 0; j < NF; j++)
#pragma unroll
            for (int k = 0; k < 4; k++) acc[i][j][k] = 0.f;

    auto issue = [&](int st, int k0) {
        uint32_t base = sbase + st * STAGE;
#pragma unroll
        for (int i = 0; i < 2; i++) {       // A: 128 rows x 4 16B groups
            int q = tid + i * 256;
            int r = q >> 2, g = q & 3;
            uint32_t d = base + r * 80 + g * 16;
            cpa16(d, Abh + (size_t)r * lda + k0 + g * 8);
            if (AFMT == 0)
                cpa16(d + 10240, Abl + (size_t)r * lda + k0 + g * 8);
        }
#pragma unroll
        for (int i = 0; i < NBI; i++) {     // B: BN rows x 4 groups, 2 planes
            int q = tid + i * 256;
            int r = q >> 2, g = q & 3;
            uint32_t d = base + ABYTES + r * 80 + g * 16;
            cpa16(d,           Bbh + (size_t)r * ldb + k0 + g * 8);
            cpa16(d + BN * 80, Bbl + (size_t)r * ldb + k0 + g * 8);
        }
        CP_COMMIT();
    };

    const int NC = K >> 5;
    issue(0, 0);

    for (int c = 0; c < NC; c++) {
        CP_WAIT0();
        __syncthreads();
        if (c + 1 < NC) issue((c + 1) & 1, (c + 1) * 32);

        const uint32_t aAh = sbase + (c & 1) * STAGE;
        const uint32_t aAl = aAh + 10240;
        const uint32_t aBh = aAh + ABYTES;
        const uint32_t aBl = aBh + BN * 80;
#pragma unroll
        for (int kk = 0; kk < 32; kk += 16) {
            uint32_t bh[NF][2], bl[NF][2];
#pragma unroll
            for (int np = 0; np < NF / 2; np++) {
                uint32_t bo = (uint32_t)((n0w + np * 16 + ((lane >> 4) << 3) +
                                          (lane & 7)) * 40 +
                                         kk + ((lane >> 3) & 1) * 8) * 2;
                ldsm4(bh[2 * np][0], bh[2 * np][1], bh[2 * np + 1][0],
                      bh[2 * np + 1][1], aBh + bo);
                ldsm4(bl[2 * np][0], bl[2 * np][1], bl[2 * np + 1][0],
                      bl[2 * np + 1][1], aBl + bo);
            }
#pragma unroll
            for (int mi = 0; mi < MF; mi++) {
                uint32_t ao = (uint32_t)((m0w + mi * 16 + (lane & 15)) * 40 +
                                         kk + ((lane >> 4) << 3)) * 2;
                uint32_t ah[4];
                ldsm4(ah[0], ah[1], ah[2], ah[3], aAh + ao);
                if (AFMT == 0) {
                    uint32_t al[4];
                    ldsm4(al[0], al[1], al[2], al[3], aAl + ao);
#pragma unroll
                    for (int ni = 0; ni < NF; ni++) {
                        mma16816(acc[mi][ni], ah, bh[ni]);
                        mma16816(acc[mi][ni], al, bh[ni]);
                        mma16816(acc[mi][ni], ah, bl[ni]);
                    }
                } else {
#pragma unroll
                    for (int ni = 0; ni < NF; ni++) {
                        mma16816(acc[mi][ni], ah, bh[ni]);
                        mma16816(acc[mi][ni], ah, bl[ni]);
                    }
                }
            }
        }
        __syncthreads();
    }

    // ---- epilogue: fragment-direct ----
#pragma unroll
    for (int ni = 0; ni < NF; ni++) {
        const int col = col0 + n0w + ni * 8 + (lane & 3) * 2;
        float2 e = make_float2(0.f, 0.f);
        if (EPI == 0 || EPI == 1) {
            e = *(const float2*)(aux + col);
        } else if (EPI == 2) {
            float2 m = *(const float2*)(aux + (size_t)zb * Ss + col);
            e.x = (1.f - m.x) * -10000.f;
            e.y = (1.f - m.y) * -10000.f;
        }
#pragma unroll
        for (int mi = 0; mi < MF; mi++) {
            const int r0g = row0 + m0w + mi * 16 + (lane >> 2);
            float* a = acc[mi][ni];
            float2 v0, v1;
            if (EPI == 2) {
                v0 = make_float2(a[0] * 0.125f + e.x, a[1] * 0.125f + e.y);
                v1 = make_float2(a[2] * 0.125f + e.x, a[3] * 0.125f + e.y);
            } else {
                v0 = make_float2(a[0] + e.x, a[1] + e.y);
                v1 = make_float2(a[2] + e.x, a[3] + e.y);
                if (EPI == 1) {
                    v0.x = fmaxf(v0.x, 0.f); v0.y = fmaxf(v0.y, 0.f);
                    v1.x = fmaxf(v1.x, 0.f); v1.y = fmaxf(v1.y, 0.f);
                }
            }
            if (CFMT == 0) {
                *(float2*)(Cb + (size_t)r0g * ldc + col) = v0;
                *(float2*)(Cb + (size_t)(r0g + 8) * ldc + col) = v1;
            } else {
                store_pair(CbH, CbL, (size_t)r0g * ldc + col, v0);
                store_pair(CbH, CbL, (size_t)(r0g + 8) * ldc + col, v1);
            }
        }
    }
}

// ---------------------------------------------------------------------------
// Split fp32 tensor into fp16 hi/lo planes
// ---------------------------------------------------------------------------
__global__ void __launch_bounds__(256) split_f32(
    const float* __restrict__ X, __half* __restrict__ H, __half* __restrict__ L)
{
    size_t i = (size_t)blockIdx.x * 256 + threadIdx.x;
    float4 v = ((const float4*)X)[i];
    store_pair(H, L, i * 4,     make_float2(v.x, v.y));
    store_pair(H, L, i * 4 + 2, make_float2(v.z, v.w));
}

// Weight transpose + split: T[c][r] = split(W[r][c])
__global__ void transpose_split(const float* __restrict__ W,
                                __half* __restrict__ TH, __half* __restrict__ TL,
                                int R, int C)
{
    __shared__ float t[32][33];
    int c0 = blockIdx.x * 32, r0 = blockIdx.y * 32;
#pragma unroll
    for (int i = threadIdx.y; i < 32; i += 8)
        t[i][threadIdx.x] = W[(size_t)(r0 + i) * C + c0 + threadIdx.x];
    __syncthreads();
#pragma unroll
    for (int i = threadIdx.y; i < 32; i += 8) {
        float v = t[threadIdx.x][i];
        __half h = __float2half_rn(v);
        size_t o = (size_t)(c0 + i) * R + r0 + threadIdx.x;
        TH[o] = h;
        TL[o] = __float2half_rn(v - __half2float(h));
    }
}

// V^T per (b,h) on pairs: Vt[bh][d][sk] = V[b][sk][h*64+d]
__global__ void vt_pairs(const __half* __restrict__ VH, const __half* __restrict__ VL,
                         __half* __restrict__ TH, __half* __restrict__ TL)
{
    __shared__ __half t[2][32][33];
    const int bh = blockIdx.z, b = bh >> 4, h = bh & 15;
    const int sk0 = blockIdx.x * 32, d0 = blockIdx.y * 32;
    const __half* vh = VH + (size_t)b * Ss * Dd + h * HDIM;
    const __half* vl = VL + (size_t)b * Ss * Dd + h * HDIM;
#pragma unroll
    for (int i = threadIdx.y; i < 32; i += 8) {
        t[0][i][threadIdx.x] = vh[(size_t)(sk0 + i) * Dd + d0 + threadIdx.x];
        t[1][i][threadIdx.x] = vl[(size_t)(sk0 + i) * Dd + d0 + threadIdx.x];
    }
    __syncthreads();
    __half* oh = TH + (size_t)bh * HDIM * Ss;
    __half* ol = TL + (size_t)bh * HDIM * Ss;
#pragma unroll
    for (int i = threadIdx.y; i < 32; i += 8) {
        oh[(size_t)(d0 + i) * Ss + sk0 + threadIdx.x] = t[0][threadIdx.x][i];
        ol[(size_t)(d0 + i) * Ss + sk0 + threadIdx.x] = t[1][threadIdx.x][i];
    }
}

// ---------------------------------------------------------------------------
// Softmax over rows of 1024: fp32 mirror (attn_weights) + single fp16 P plane
// ---------------------------------------------------------------------------
__global__ void __launch_bounds__(256) softmax_kernel(
    const float* __restrict__ S, float* __restrict__ ext,
    __half* __restrict__ PH)
{
    __shared__ float sbuf[8];
    const size_t row = blockIdx.x;
    const float* p = S + row * Ss;
    const int tid = threadIdx.x;
    const int lane = tid & 31, w = tid >> 5;

    float4 x = *(const float4*)(p + tid * 4);
    float m = fmaxf(fmaxf(x.x, x.y), fmaxf(x.z, x.w));
#pragma unroll
    for (int o = 16; o > 0; o >>= 1) m = fmaxf(m, __shfl_xor_sync(~0u, m, o));
    if (lane == 0) sbuf[w] = m;
    __syncthreads();
    m = sbuf[0];
#pragma unroll
    for (int i = 1; i < 8; i++) m = fmaxf(m, sbuf[i]);

    float4 e;
    e.x = expf(x.x - m); e.y = expf(x.y - m);
    e.z = expf(x.z - m); e.w = expf(x.w - m);
    float s = e.x + e.y + e.z + e.w;
#pragma unroll
    for (int o = 16; o > 0; o >>= 1) s += __shfl_xor_sync(~0u, s, o);
    __syncthreads();
    if (lane == 0) sbuf[w] = s;
    __syncthreads();
    s = 0.f;
#pragma unroll
    for (int i = 0; i < 8; i++) s += sbuf[i];
    float inv = 1.0f / s;
    e.x *= inv; e.y *= inv; e.z *= inv; e.w *= inv;
    if (ext) *(float4*)(ext + row * Ss + tid * 4) = e;
    __half2 p0 = __floats2half2_rn(e.x, e.y);
    __half2 p1 = __floats2half2_rn(e.z, e.w);
    *(__half2*)(PH + row * Ss + tid * 4)     = p0;
    *(__half2*)(PH + row * Ss + tid * 4 + 2) = p1;
}

// ---------------------------------------------------------------------------
// LayerNorm kernels
// ---------------------------------------------------------------------------
__device__ __forceinline__ float block_sum(float v, float* sbuf) {
    const int lane = threadIdx.x & 31, w = threadIdx.x >> 5;
#pragma unroll
    for (int o = 16; o > 0; o >>= 1) v += __shfl_xor_sync(~0u, v, o);
    __syncthreads();
    if (lane == 0) sbuf[w] = v;
    __syncthreads();
    float s = 0.f;
#pragma unroll
    for (int i = 0; i < 8; i++) s += sbuf[i];
    return s;
}

// t = X + q ; ln1 = LN(t,1e-8) ; t2 = q + ln1 ; out = LN(t2,1e-6)
__global__ void __launch_bounds__(256) ln_a_kernel(
    const float* __restrict__ X, const float* __restrict__ q,
    const float* __restrict__ g1, const float* __restrict__ b1,
    const float* __restrict__ g2, const float* __restrict__ b2,
    float* __restrict__ out, __half* __restrict__ OH, __half* __restrict__ OL)
{
    __shared__ float sbuf[8];
    const size_t row = blockIdx.x;
    const int col = threadIdx.x * 4;
    float4 xv = *(const float4*)(X + row * Dd + col);
    float4 qv = *(const float4*)(q + row * Dd + col);
    float t[4] = { xv.x + qv.x, xv.y + qv.y, xv.z + qv.z, xv.w + qv.w };

    float mu = block_sum(t[0] + t[1] + t[2] + t[3], sbuf) * (1.0f / Dd);
    float ss = 0.f;
#pragma unroll
    for (int i = 0; i < 4; i++) { float d = t[i] - mu; ss += d * d; }
    float var = block_sum(ss, sbuf) * (1.0f / Dd);
    float inv = rsqrtf(var + 1e-8f);

    float4 g = *(const float4*)(g1 + col);
    float4 be = *(const float4*)(b1 + col);
    float qarr[4] = { qv.x, qv.y, qv.z, qv.w };
    float garr[4] = { g.x, g.y, g.z, g.w };
    float barr[4] = { be.x, be.y, be.z, be.w };
    float t2[4];
#pragma unroll
    for (int i = 0; i < 4; i++)
        t2[i] = qarr[i] + (t[i] - mu) * inv * garr[i] + barr[i];

    float mu2 = block_sum(t2[0] + t2[1] + t2[2] + t2[3], sbuf) * (1.0f / Dd);
    float ss2 = 0.f;
#pragma unroll
    for (int i = 0; i < 4; i++) { float d = t2[i] - mu2; ss2 += d * d; }
    float var2 = block_sum(ss2, sbuf) * (1.0f / Dd);
    float inv2 = rsqrtf(var2 + 1e-6f);

    g = *(const float4*)(g2 + col);
    be = *(const float4*)(b2 + col);
    float4 o;
    o.x = (t2[0] - mu2) * inv2 * g.x + be.x;
    o.y = (t2[1] - mu2) * inv2 * g.y + be.y;
    o.z = (t2[2] - mu2) * inv2 * g.z + be.z;
    o.w = (t2[3] - mu2) * inv2 * g.w + be.w;
    *(float4*)(out + row * Dd + col) = o;
    store_pair(OH, OL, row * Dd + col,     make_float2(o.x, o.y));
    store_pair(OH, OL, row * Dd + col + 2, make_float2(o.z, o.w));
}

__global__ void __launch_bounds__(256) ln_b_kernel(
    const float* __restrict__ Z, const float* __restrict__ res,
    const float* __restrict__ g1, const float* __restrict__ b1,
    float* __restrict__ out)
{
    __shared__ float sbuf[8];
    const size_t row = blockIdx.x;
    const int col = threadIdx.x * 4;
    float4 zv = *(const float4*)(Z + row * Dd + col);
    float4 rv = *(const float4*)(res + row * Dd + col);
    float t[4] = { zv.x + rv.x, zv.y + rv.y, zv.z + rv.z, zv.w + rv.w };

    float mu = block_sum(t[0] + t[1] + t[2] + t[3], sbuf) * (1.0f / Dd);
    float ss = 0.f;
#pragma unroll
    for (int i = 0; i < 4; i++) { float d = t[i] - mu; ss += d * d; }
    float var = block_sum(ss, sbuf) * (1.0f / Dd);
    float inv = rsqrtf(var + 1e-6f);

    float4 g = *(const float4*)(g1 + col);
    float4 be = *(const float4*)(b1 + col);
    float4 o;
    o.x = (t[0] - mu) * inv * g.x + be.x;
    o.y = (t[1] - mu) * inv * g.y + be.y;
    o.z = (t[2] - mu) * inv * g.z + be.z;
    o.w = (t[3] - mu) * inv * g.w + be.w;
    *(float4*)(out + row * Dd + col) = o;
}

// ---------------------------------------------------------------------------
// kernel_launch
// ---------------------------------------------------------------------------
extern "C" void kernel_launch(void* const* d_in, const int* in_sizes, int n_in,
                              void* d_out, int out_size)
{
    const float* query = (const float*)d_in[0];
    const float* key   = (const float*)d_in[1];
    const float* value = (const float*)d_in[2];
    const float* mask  = (const float*)d_in[3];
    const float* wq = (const float*)d_in[4];
    const float* bq = (const float*)d_in[5];
    const float* wk = (const float*)d_in[6];
    const float* bk = (const float*)d_in[7];
    const float* wv = (const float*)d_in[8];
    const float* bv = (const float*)d_in[9];
    const float* wo = (const float*)d_in[10];
    const float* bo = (const float*)d_in[11];
    const float* ln_mha_g = (const float*)d_in[12];
    const float* ln_mha_b = (const float*)d_in[13];
    const float* w1 = (const float*)d_in[14];
    const float* b1 = (const float*)d_in[15];
    const float* w2 = (const float*)d_in[16];
    const float* b2 = (const float*)d_in[17];
    const float* ln_attn_g = (const float*)d_in[18];
    const float* ln_attn_b = (const float*)d_in[19];
    const float* ln_ffn_g = (const float*)d_in[20];
    const float* ln_ffn_b = (const float*)d_in[21];
    (void)in_sizes; (void)n_in;

    float* out = (float*)d_out;

    __half *qp, *kp, *vp, *Qp, *Kp, *Vp, *Vtp, *ctx, *aop, *Fp, *Ph, *WTp;
    float *S, *X, *ao, *Z;
    cudaGetSymbolAddress((void**)&qp, g_qp);
    cudaGetSymbolAddress((void**)&kp, g_kp);
    cudaGetSymbolAddress((void**)&vp, g_vp);
    cudaGetSymbolAddress((void**)&Qp, g_Qp);
    cudaGetSymbolAddress((void**)&Kp, g_Kp);
    cudaGetSymbolAddress((void**)&Vp, g_Vp);
    cudaGetSymbolAddress((void**)&Vtp, g_Vtp);
    cudaGetSymbolAddress((void**)&ctx, g_ctx);
    cudaGetSymbolAddress((void**)&aop, g_aop);
    cudaGetSymbolAddress((void**)&Fp, g_Fp);
    cudaGetSymbolAddress((void**)&Ph, g_Ph);
    cudaGetSymbolAddress((void**)&WTp, g_WTp);
    cudaGetSymbolAddress((void**)&S, g_S);
    cudaGetSymbolAddress((void**)&X, g_X);
    cudaGetSymbolAddress((void**)&ao, g_ao);
    cudaGetSymbolAddress((void**)&Z, g_Z);

    const size_t nMD = (size_t)Mm * Dd;
    const size_t nMF = (size_t)Mm * Ff;
    const size_t nS  = (size_t)Bb * Hh * Ss * Ss;
    const size_t nVt = (size_t)Bb * Hh * HDIM * Ss;

    __half *qpH = qp, *qpL = qp + nMD;
    __half *kpH = kp, *kpL = kp + nMD;
    __half *vpH = vp, *vpL = vp + nMD;
    __half *QpH = Qp, *QpL = Qp + nMD;
    __half *KpH = Kp, *KpL = Kp + nMD;
    __half *VpH = Vp, *VpL = Vp + nMD;
    __half *VtH = Vtp, *VtL = Vtp + nVt;
    __half *cxH = ctx, *cxL = ctx + nMD;
    __half *aoH = aop, *aoL = aop + nMD;
    __half *FpH = Fp, *FpL = Fp + nMF;

    const size_t wsz = (size_t)4 * Dd * Dd + (size_t)Dd * Ff + (size_t)Ff * Dd;
    __half* WTh = WTp;          __half* WTl = WTp + wsz;
    __half *wqTH = WTh,                      *wqTL = WTl;
    __half *wkTH = WTh + (size_t)Dd * Dd,    *wkTL = WTl + (size_t)Dd * Dd;
    __half *wvTH = WTh + (size_t)2 * Dd * Dd,*wvTL = WTl + (size_t)2 * Dd * Dd;
    __half *woTH = WTh + (size_t)3 * Dd * Dd,*woTL = WTl + (size_t)3 * Dd * Dd;
    __half *w1TH = WTh + (size_t)4 * Dd * Dd,*w1TL = WTl + (size_t)4 * Dd * Dd;
    __half *w2TH = w1TH + (size_t)Dd * Ff,   *w2TL = w1TL + (size_t)Dd * Ff;

    const long long main_elems = (long long)Mm * Dd;
    const long long attn_elems = (long long)nS;
    float* attn_ext = ((long long)out_size >= main_elems + attn_elems)
                          ? (out + main_elems) : nullptr;

    // BN=256: stage = 20480 + 256*160 = 61440 ; 2 stages = 122880 (1 CTA/SM)
    const int DSZ256 = 2 * (20480 + 256 * 160);
    const int DSZ64A = 2 * (10240 + 64 * 160);    // 40960 (PV, AFMT=2)
    cudaFuncSetAttribute(gemm_ps<256,0,1,0>, cudaFuncAttributeMaxDynamicSharedMemorySize, DSZ256);
    cudaFuncSetAttribute(gemm_ps<256,0,0,0>, cudaFuncAttributeMaxDynamicSharedMemorySize, DSZ256);
    cudaFuncSetAttribute(gemm_ps<256,1,1,0>, cudaFuncAttributeMaxDynamicSharedMemorySize, DSZ256);
    cudaFuncSetAttribute(gemm_ps<256,2,0,0>, cudaFuncAttributeMaxDynamicSharedMemorySize, DSZ256);
    cudaFuncSetAttribute(gemm_ps<64,3,1,2>,  cudaFuncAttributeMaxDynamicSharedMemorySize, DSZ64A);

    dim3 tblk(32, 8);

    split_f32<<<nMD / 1024, 256>>>(query, qpH, qpL);
    split_f32<<<nMD / 1024, 256>>>(key,   kpH, kpL);
    split_f32<<<nMD / 1024, 256>>>(value, vpH, vpL);
    transpose_split<<<dim3(Dd/32, Dd/32), tblk>>>(wq, wqTH, wqTL, Dd, Dd);
    transpose_split<<<dim3(Dd/32, Dd/32), tblk>>>(wk, wkTH, wkTL, Dd, Dd);
    transpose_split<<<dim3(Dd/32, Dd/32), tblk>>>(wv, wvTH, wvTL, Dd, Dd);
    transpose_split<<<dim3(Dd/32, Dd/32), tblk>>>(wo, woTH, woTL, Dd, Dd);
    transpose_split<<<dim3(Ff/32, Dd/32), tblk>>>(w1, w1TH, w1TL, Dd, Ff);
    transpose_split<<<dim3(Dd/32, Ff/32), tblk>>>(w2, w2TH, w2TL, Ff, Dd);

    // QKV projections -> pairs
    gemm_ps<256,0,1,0><<<dim3(Dd/256, Mm/128, 1), 256, DSZ256>>>(
        qpH, qpL, Dd, 0, 0, wqTH, wqTL, Dd, 0, 0,
        nullptr, QpH, QpL, Dd, 0, 0, bq, Dd);
    gemm_ps<256,0,1,0><<<dim3(Dd/256, Mm/128, 1), 256, DSZ256>>>(
        kpH, kpL, Dd, 0, 0, wkTH, wkTL, Dd, 0, 0,
        nullptr, KpH, KpL, Dd, 0, 0, bk, Dd);
    gemm_ps<256,0,1,0><<<dim3(Dd/256, Mm/128, 1), 256, DSZ256>>>(
        vpH, vpL, Dd, 0, 0, wvTH, wvTL, Dd, 0, 0,
        nullptr, VpH, VpL, Dd, 0, 0, bv, Dd);

    // V^T per head (pairs)
    vt_pairs<<<dim3(Ss/32, HDIM/32, Bb*Hh), tblk>>>(VpH, VpL, VtH, VtL);

    // scores = QK^T/8 + mask -> fp32 S
    gemm_ps<256,2,0,0><<<dim3(Ss/256, Ss/128, Bb*Hh), 256, DSZ256>>>(
        QpH, QpL, Dd, (long long)Ss*Dd, HDIM,
        KpH, KpL, Dd, (long long)Ss*Dd, HDIM,
        S, nullptr, nullptr, Ss, 16LL*Ss*Ss, (long long)Ss*Ss,
        mask, HDIM);

    // softmax -> attn_weights mirror + single-plane fp16 P
    softmax_kernel<<<Bb*Hh*Ss, 256>>>(S, attn_ext, Ph);

    // context = P @ V -> pairs (A = single fp16 plane)
    gemm_ps<64,3,1,2><<<dim3(1, Ss/128, Bb*Hh), 256, DSZ64A>>>(
        Ph, nullptr, Ss, 16LL*Ss*Ss, (long long)Ss*Ss,
        VtH, VtL, Ss, 16LL*HDIM*Ss, (long long)HDIM*Ss,
        nullptr, cxH, cxL, Dd, (long long)Ss*Dd, HDIM,
        nullptr, Ss);

    // O-projection -> fp32 X
    gemm_ps<256,0,0,0><<<dim3(Dd/256, Mm/128, 1), 256, DSZ256>>>(
        cxH, cxL, Dd, 0, 0, woTH, woTL, Dd, 0, 0,
        X, nullptr, nullptr, Dd, 0, 0, bo, Dd);

    // Double LayerNorm -> attn_out fp32 + pairs
    ln_a_kernel<<<Mm, 256>>>(X, query, ln_mha_g, ln_mha_b,
                             ln_attn_g, ln_attn_b, ao, aoH, aoL);

    // FFN1 -> F pairs (relu)
    gemm_ps<256,1,1,0><<<dim3(Ff/256, Mm/128, 1), 256, DSZ256>>>(
        aoH, aoL, Dd, 0, 0, w1TH, w1TL, Dd, 0, 0,
        nullptr, FpH, FpL, Ff, 0, 0, b1, Dd);

    // FFN2 -> fp32 Z
    gemm_ps<256,0,0,0><<<dim3(Dd/256, Mm/128, 1), 256, DSZ256>>>(
        FpH, FpL, Ff, 0, 0, w2TH, w2TL, Ff, 0, 0,
        Z, nullptr, nullptr, Dd, 0, 0, b2, Ff);

    // Final LayerNorm -> main output
    ln_b_kernel<<<Mm, 256>>>(Z, ao, ln_ffn_g, ln_ffn_b, out);
}

// round 7
// speedup vs baseline: 1.4127x; 1.4127x over previous
#include <cuda_runtime.h>
#include <cuda_fp16.h>
#include <math.h>
#include <stdint.h>

#define Bb 8
#define Ss 1024
#define Dd 1024
#define Hh 16
#define HDIM 64
#define Ff 4096
#define Mm (Bb*Ss)

// ---------------------------------------------------------------------------
// Scratch (device globals). Pair tensors: [0..n) hi plane, [n..2n) lo plane.
// Activations are single-plane fp16; B-side operands (weights, K, Vt) pairs.
// ---------------------------------------------------------------------------
__device__ __half g_qh [(size_t)Mm*Dd];            // query fp16
__device__ __half g_kh [(size_t)Mm*Dd];            // key fp16
__device__ __half g_vh [(size_t)Mm*Dd];            // value fp16
__device__ __half g_Qh [(size_t)Mm*Dd];            // Q proj (A of scores)
__device__ __half g_Kp [2*(size_t)Mm*Dd];          // K proj (B of scores) pair
__device__ __half g_Vp [2*(size_t)Mm*Dd];          // V proj pair
__device__ __half g_Vtp[2*(size_t)Bb*Hh*HDIM*Ss];  // V^T pair (B of PV)
__device__ __half g_cth[(size_t)Mm*Dd];            // context fp16 (A of O-proj)
__device__ __half g_aoh[(size_t)Mm*Dd];            // attn_out fp16 (A of FFN1)
__device__ __half g_Fh [(size_t)Mm*Ff];            // FFN mid fp16 (A of FFN2)
__device__ __half g_Ph [(size_t)Bb*Hh*Ss*Ss];      // P fp16 (A of PV)
__device__ __half g_WTp[2*(size_t)(4*Dd*Dd + Dd*Ff + Ff*Dd)];
__device__ float  g_S  [(size_t)Bb*Hh*Ss*Ss];
__device__ float  g_X  [(size_t)Mm*Dd];
__device__ float  g_ao [(size_t)Mm*Dd];
__device__ float  g_Z  [(size_t)Mm*Dd];

// ---------------------------------------------------------------------------
// PTX helpers (baseline sm_80+ features, valid on plain sm_103 target)
// ---------------------------------------------------------------------------
__device__ __forceinline__ uint32_t smem_u32(const void* p) {
    uint32_t a;
    asm("{ .reg .u64 t; cvta.to.shared.u64 t, %1; cvt.u32.u64 %0, t; }"
        : "=r"(a) : "l"(p));
    return a;
}
__device__ __forceinline__ void ldsm4(uint32_t& r0, uint32_t& r1, uint32_t& r2,
                                      uint32_t& r3, uint32_t addr) {
    asm volatile("ldmatrix.sync.aligned.m8n8.x4.shared.b16 {%0,%1,%2,%3}, [%4];"
                 : "=r"(r0), "=r"(r1), "=r"(r2), "=r"(r3) : "r"(addr));
}
__device__ __forceinline__ void mma16816(float* d, const uint32_t* a,
                                         const uint32_t* b) {
    asm volatile(
        "mma.sync.aligned.m16n8k16.row.col.f32.f16.f16.f32 "
        "{%0,%1,%2,%3}, {%4,%5,%6,%7}, {%8,%9}, {%0,%1,%2,%3};"
        : "+f"(d[0]), "+f"(d[1]), "+f"(d[2]), "+f"(d[3])
        : "r"(a[0]), "r"(a[1]), "r"(a[2]), "r"(a[3]), "r"(b[0]), "r"(b[1]));
}
__device__ __forceinline__ void cpa16(uint32_t dst, const void* src) {
    asm volatile("cp.async.cg.shared.global [%0], [%1], 16;"
                 :: "r"(dst), "l"(src) : "memory");
}
#define CP_COMMIT() asm volatile("cp.async.commit_group;" ::: "memory")
#define CP_WAIT0()  asm volatile("cp.async.wait_group 0;" ::: "memory")

// fp32 pair split store: hi = f16(x), lo = f16(x - hi)
__device__ __forceinline__ void store_pair(__half* H, __half* L, size_t off,
                                           float2 v) {
    __half2 h = __floats2half2_rn(v.x, v.y);
    float2 hf = __half22float2(h);
    __half2 l = __floats2half2_rn(v.x - hf.x, v.y - hf.y);
    *(__half2*)(H + off) = h;
    *(__half2*)(L + off) = l;
}

// ---------------------------------------------------------------------------
// GEMM: C[128 x BN] = A[128,K] @ B[BN,K]^T, fp32 accum.
//   A single fp16 plane; B hi/lo pair -> D = A*Bh + A*Bl  (2 MMAs)
//   2-stage cp.async pipeline, 2 CTAs/SM. Warp grid 2(m) x 4(n).
//   Batch via blockIdx.z: off = (z>>4)*s1 + (z&15)*s2 (elements per plane).
//   EPI: 0=+bias  1=+bias,relu  2=scores(x/8+(1-mask)*-1e4)  3=plain
//   CFMT: 0 = fp32 out (C) ; 1 = fp16 pair out (CH/CL) ; 2 = fp16 single (CH)
// ---------------------------------------------------------------------------
template<int BN, int EPI, int CFMT>
__global__ void __launch_bounds__(256, 2) gemm_ps(
    const __half* __restrict__ AH,
    long long lda, long long a1, long long a2,
    const __half* __restrict__ BH, const __half* __restrict__ BL,
    long long ldb, long long b1, long long b2,
    float* __restrict__ C, __half* __restrict__ CH, __half* __restrict__ CL,
    long long ldc, long long c1, long long c2,
    const float* __restrict__ aux, int K)
{
    constexpr int MF = 4;                 // m16 frags per warp (m span 64)
    constexpr int NF = BN / 32;           // n8 frags per warp (n span BN/4)
    constexpr int NBI = BN / 64;          // B cp.async iters per plane
    constexpr int ABYTES = 10240;
    constexpr int STAGE = ABYTES + BN * 160;

    extern __shared__ char dsm[];

    const int tid = threadIdx.x, lane = tid & 31, wid = tid >> 5;
    const int zb = blockIdx.z >> 4, zh = blockIdx.z & 15;
    const int row0 = blockIdx.y * 128, col0 = blockIdx.x * BN;
    const int m0w = (wid >> 2) * 64, n0w = (wid & 3) * (BN / 4);

    const __half* Abh = AH + zb * a1 + zh * a2 + (size_t)row0 * lda;
    const __half* Bbh = BH + zb * b1 + zh * b2 + (size_t)col0 * ldb;
    const __half* Bbl = BL + zb * b1 + zh * b2 + (size_t)col0 * ldb;
    float* Cb = C + zb * c1 + zh * c2;
    __half* CbH = CH + zb * c1 + zh * c2;
    __half* CbL = CL + zb * c1 + zh * c2;

    const uint32_t sbase = smem_u32(dsm);

    float acc[MF][NF][4];
#pragma unroll
    for (int i = 0; i < MF; i++)
#pragma unroll
        for (int j = 0; j < NF; j++)
#pragma unroll
            for (int k = 0; k < 4; k++) acc[i][j][k] = 0.f;

    auto issue = [&](int st, int k0) {
        uint32_t base = sbase + st * STAGE;
#pragma unroll
        for (int i = 0; i < 2; i++) {       // A: 128 rows x 4 16B groups
            int q = tid + i * 256;
            int r = q >> 2, g = q & 3;
            cpa16(base + r * 80 + g * 16, Abh + (size_t)r * lda + k0 + g * 8);
        }
#pragma unroll
        for (int i = 0; i < NBI; i++) {     // B: BN rows x 4 groups, 2 planes
            int q = tid + i * 256;
            int r = q >> 2, g = q & 3;
            uint32_t d = base + ABYTES + r * 80 + g * 16;
            cpa16(d,           Bbh + (size_t)r * ldb + k0 + g * 8);
            cpa16(d + BN * 80, Bbl + (size_t)r * ldb + k0 + g * 8);
        }
        CP_COMMIT();
    };

    const int NC = K >> 5;
    issue(0, 0);

    for (int c = 0; c < NC; c++) {
        CP_WAIT0();
        __syncthreads();
        if (c + 1 < NC) issue((c + 1) & 1, (c + 1) * 32);

        const uint32_t aAh = sbase + (c & 1) * STAGE;
        const uint32_t aBh = aAh + ABYTES;
        const uint32_t aBl = aBh + BN * 80;
#pragma unroll
        for (int kk = 0; kk < 32; kk += 16) {
            uint32_t bh[NF][2], bl[NF][2];
#pragma unroll
            for (int np = 0; np < NF / 2; np++) {
                uint32_t bo = (uint32_t)((n0w + np * 16 + ((lane >> 4) << 3) +
                                          (lane & 7)) * 40 +
                                         kk + ((lane >> 3) & 1) * 8) * 2;
                ldsm4(bh[2 * np][0], bh[2 * np][1], bh[2 * np + 1][0],
                      bh[2 * np + 1][1], aBh + bo);
                ldsm4(bl[2 * np][0], bl[2 * np][1], bl[2 * np + 1][0],
                      bl[2 * np + 1][1], aBl + bo);
            }
#pragma unroll
            for (int mi = 0; mi < MF; mi++) {
                uint32_t ao = (uint32_t)((m0w + mi * 16 + (lane & 15)) * 40 +
                                         kk + ((lane >> 4) << 3)) * 2;
                uint32_t ah[4];
                ldsm4(ah[0], ah[1], ah[2], ah[3], aAh + ao);
#pragma unroll
                for (int ni = 0; ni < NF; ni++) {
                    mma16816(acc[mi][ni], ah, bh[ni]);
                    mma16816(acc[mi][ni], ah, bl[ni]);
                }
            }
        }
        __syncthreads();
    }

    // ---- epilogue: fragment-direct ----
#pragma unroll
    for (int ni = 0; ni < NF; ni++) {
        const int col = col0 + n0w + ni * 8 + (lane & 3) * 2;
        float2 e = make_float2(0.f, 0.f);
        if (EPI == 0 || EPI == 1) {
            e = *(const float2*)(aux + col);
        } else if (EPI == 2) {
            float2 m = *(const float2*)(aux + (size_t)zb * Ss + col);
            e.x = (1.f - m.x) * -10000.f;
            e.y = (1.f - m.y) * -10000.f;
        }
#pragma unroll
        for (int mi = 0; mi < MF; mi++) {
            const int r0g = row0 + m0w + mi * 16 + (lane >> 2);
            float* a = acc[mi][ni];
            float2 v0, v1;
            if (EPI == 2) {
                v0 = make_float2(a[0] * 0.125f + e.x, a[1] * 0.125f + e.y);
                v1 = make_float2(a[2] * 0.125f + e.x, a[3] * 0.125f + e.y);
            } else {
                v0 = make_float2(a[0] + e.x, a[1] + e.y);
                v1 = make_float2(a[2] + e.x, a[3] + e.y);
                if (EPI == 1) {
                    v0.x = fmaxf(v0.x, 0.f); v0.y = fmaxf(v0.y, 0.f);
                    v1.x = fmaxf(v1.x, 0.f); v1.y = fmaxf(v1.y, 0.f);
                }
            }
            if (CFMT == 0) {
                *(float2*)(Cb + (size_t)r0g * ldc + col) = v0;
                *(float2*)(Cb + (size_t)(r0g + 8) * ldc + col) = v1;
            } else if (CFMT == 1) {
                store_pair(CbH, CbL, (size_t)r0g * ldc + col, v0);
                store_pair(CbH, CbL, (size_t)(r0g + 8) * ldc + col, v1);
            } else {
                *(__half2*)(CbH + (size_t)r0g * ldc + col) =
                    __floats2half2_rn(v0.x, v0.y);
                *(__half2*)(CbH + (size_t)(r0g + 8) * ldc + col) =
                    __floats2half2_rn(v1.x, v1.y);
            }
        }
    }
}

// ---------------------------------------------------------------------------
// Convert fp32 tensor to single fp16 plane
// ---------------------------------------------------------------------------
__global__ void __launch_bounds__(256) convert_f16(
    const float* __restrict__ X, __half* __restrict__ H)
{
    size_t i = (size_t)blockIdx.x * 256 + threadIdx.x;
    float4 v = ((const float4*)X)[i];
    *(__half2*)(H + i * 4)     = __floats2half2_rn(v.x, v.y);
    *(__half2*)(H + i * 4 + 2) = __floats2half2_rn(v.z, v.w);
}

// Weight transpose + split: T[c][r] = split(W[r][c])
__global__ void transpose_split(const float* __restrict__ W,
                                __half* __restrict__ TH, __half* __restrict__ TL,
                                int R, int C)
{
    __shared__ float t[32][33];
    int c0 = blockIdx.x * 32, r0 = blockIdx.y * 32;
#pragma unroll
    for (int i = threadIdx.y; i < 32; i += 8)
        t[i][threadIdx.x] = W[(size_t)(r0 + i) * C + c0 + threadIdx.x];
    __syncthreads();
#pragma unroll
    for (int i = threadIdx.y; i < 32; i += 8) {
        float v = t[threadIdx.x][i];
        __half h = __float2half_rn(v);
        size_t o = (size_t)(c0 + i) * R + r0 + threadIdx.x;
        TH[o] = h;
        TL[o] = __float2half_rn(v - __half2float(h));
    }
}

// V^T per (b,h) on pairs: Vt[bh][d][sk] = V[b][sk][h*64+d]
__global__ void vt_pairs(const __half* __restrict__ VH, const __half* __restrict__ VL,
                         __half* __restrict__ TH, __half* __restrict__ TL)
{
    __shared__ __half t[2][32][33];
    const int bh = blockIdx.z, b = bh >> 4, h = bh & 15;
    const int sk0 = blockIdx.x * 32, d0 = blockIdx.y * 32;
    const __half* vh = VH + (size_t)b * Ss * Dd + h * HDIM;
    const __half* vl = VL + (size_t)b * Ss * Dd + h * HDIM;
#pragma unroll
    for (int i = threadIdx.y; i < 32; i += 8) {
        t[0][i][threadIdx.x] = vh[(size_t)(sk0 + i) * Dd + d0 + threadIdx.x];
        t[1][i][threadIdx.x] = vl[(size_t)(sk0 + i) * Dd + d0 + threadIdx.x];
    }
    __syncthreads();
    __half* oh = TH + (size_t)bh * HDIM * Ss;
    __half* ol = TL + (size_t)bh * HDIM * Ss;
#pragma unroll
    for (int i = threadIdx.y; i < 32; i += 8) {
        oh[(size_t)(d0 + i) * Ss + sk0 + threadIdx.x] = t[0][threadIdx.x][i];
        ol[(size_t)(d0 + i) * Ss + sk0 + threadIdx.x] = t[1][threadIdx.x][i];
    }
}

// ---------------------------------------------------------------------------
// Softmax over rows of 1024: fp32 mirror (attn_weights) + single fp16 P plane
// ---------------------------------------------------------------------------
__global__ void __launch_bounds__(256) softmax_kernel(
    const float* __restrict__ S, float* __restrict__ ext,
    __half* __restrict__ PH)
{
    __shared__ float sbuf[8];
    const size_t row = blockIdx.x;
    const float* p = S + row * Ss;
    const int tid = threadIdx.x;
    const int lane = tid & 31, w = tid >> 5;

    float4 x = *(const float4*)(p + tid * 4);
    float m = fmaxf(fmaxf(x.x, x.y), fmaxf(x.z, x.w));
#pragma unroll
    for (int o = 16; o > 0; o >>= 1) m = fmaxf(m, __shfl_xor_sync(~0u, m, o));
    if (lane == 0) sbuf[w] = m;
    __syncthreads();
    m = sbuf[0];
#pragma unroll
    for (int i = 1; i < 8; i++) m = fmaxf(m, sbuf[i]);

    float4 e;
    e.x = expf(x.x - m); e.y = expf(x.y - m);
    e.z = expf(x.z - m); e.w = expf(x.w - m);
    float s = e.x + e.y + e.z + e.w;
#pragma unroll
    for (int o = 16; o > 0; o >>= 1) s += __shfl_xor_sync(~0u, s, o);
    __syncthreads();
    if (lane == 0) sbuf[w] = s;
    __syncthreads();
    s = 0.f;
#pragma unroll
    for (int i = 0; i < 8; i++) s += sbuf[i];
    float inv = 1.0f / s;
    e.x *= inv; e.y *= inv; e.z *= inv; e.w *= inv;
    if (ext) *(float4*)(ext + row * Ss + tid * 4) = e;
    *(__half2*)(PH + row * Ss + tid * 4)     = __floats2half2_rn(e.x, e.y);
    *(__half2*)(PH + row * Ss + tid * 4 + 2) = __floats2half2_rn(e.z, e.w);
}

// ---------------------------------------------------------------------------
// LayerNorm kernels
// ---------------------------------------------------------------------------
__device__ __forceinline__ float block_sum(float v, float* sbuf) {
    const int lane = threadIdx.x & 31, w = threadIdx.x >> 5;
#pragma unroll
    for (int o = 16; o > 0; o >>= 1) v += __shfl_xor_sync(~0u, v, o);
    __syncthreads();
    if (lane == 0) sbuf[w] = v;
    __syncthreads();
    float s = 0.f;
#pragma unroll
    for (int i = 0; i < 8; i++) s += sbuf[i];
    return s;
}

// t = X + q ; ln1 = LN(t,1e-8) ; t2 = q + ln1 ; out = LN(t2,1e-6)
__global__ void __launch_bounds__(256) ln_a_kernel(
    const float* __restrict__ X, const float* __restrict__ q,
    const float* __restrict__ g1, const float* __restrict__ b1,
    const float* __restrict__ g2, const float* __restrict__ b2,
    float* __restrict__ out, __half* __restrict__ OH)
{
    __shared__ float sbuf[8];
    const size_t row = blockIdx.x;
    const int col = threadIdx.x * 4;
    float4 xv = *(const float4*)(X + row * Dd + col);
    float4 qv = *(const float4*)(q + row * Dd + col);
    float t[4] = { xv.x + qv.x, xv.y + qv.y, xv.z + qv.z, xv.w + qv.w };

    float mu = block_sum(t[0] + t[1] + t[2] + t[3], sbuf) * (1.0f / Dd);
    float ss = 0.f;
#pragma unroll
    for (int i = 0; i < 4; i++) { float d = t[i] - mu; ss += d * d; }
    float var = block_sum(ss, sbuf) * (1.0f / Dd);
    float inv = rsqrtf(var + 1e-8f);

    float4 g = *(const float4*)(g1 + col);
    float4 be = *(const float4*)(b1 + col);
    float qarr[4] = { qv.x, qv.y, qv.z, qv.w };
    float garr[4] = { g.x, g.y, g.z, g.w };
    float barr[4] = { be.x, be.y, be.z, be.w };
    float t2[4];
#pragma unroll
    for (int i = 0; i < 4; i++)
        t2[i] = qarr[i] + (t[i] - mu) * inv * garr[i] + barr[i];

    float mu2 = block_sum(t2[0] + t2[1] + t2[2] + t2[3], sbuf) * (1.0f / Dd);
    float ss2 = 0.f;
#pragma unroll
    for (int i = 0; i < 4; i++) { float d = t2[i] - mu2; ss2 += d * d; }
    float var2 = block_sum(ss2, sbuf) * (1.0f / Dd);
    float inv2 = rsqrtf(var2 + 1e-6f);

    g = *(const float4*)(g2 + col);
    be = *(const float4*)(b2 + col);
    float4 o;
    o.x = (t2[0] - mu2) * inv2 * g.x + be.x;
    o.y = (t2[1] - mu2) * inv2 * g.y + be.y;
    o.z = (t2[2] - mu2) * inv2 * g.z + be.z;
    o.w = (t2[3] - mu2) * inv2 * g.w + be.w;
    *(float4*)(out + row * Dd + col) = o;
    *(__half2*)(OH + row * Dd + col)     = __floats2half2_rn(o.x, o.y);
    *(__half2*)(OH + row * Dd + col + 2) = __floats2half2_rn(o.z, o.w);
}

__global__ void __launch_bounds__(256) ln_b_kernel(
    const float* __restrict__ Z, const float* __restrict__ res,
    const float* __restrict__ g1, const float* __restrict__ b1,
    float* __restrict__ out)
{
    __shared__ float sbuf[8];
    const size_t row = blockIdx.x;
    const int col = threadIdx.x * 4;
    float4 zv = *(const float4*)(Z + row * Dd + col);
    float4 rv = *(const float4*)(res + row * Dd + col);
    float t[4] = { zv.x + rv.x, zv.y + rv.y, zv.z + rv.z, zv.w + rv.w };

    float mu = block_sum(t[0] + t[1] + t[2] + t[3], sbuf) * (1.0f / Dd);
    float ss = 0.f;
#pragma unroll
    for (int i = 0; i < 4; i++) { float d = t[i] - mu; ss += d * d; }
    float var = block_sum(ss, sbuf) * (1.0f / Dd);
    float inv = rsqrtf(var + 1e-6f);

    float4 g = *(const float4*)(g1 + col);
    float4 be = *(const float4*)(b1 + col);
    float4 o;
    o.x = (t[0] - mu) * inv * g.x + be.x;
    o.y = (t[1] - mu) * inv * g.y + be.y;
    o.z = (t[2] - mu) * inv * g.z + be.z;
    o.w = (t[3] - mu) * inv * g.w + be.w;
    *(float4*)(out + row * Dd + col) = o;
}

// ---------------------------------------------------------------------------
// kernel_launch
// ---------------------------------------------------------------------------
extern "C" void kernel_launch(void* const* d_in, const int* in_sizes, int n_in,
                              void* d_out, int out_size)
{
    const float* query = (const float*)d_in[0];
    const float* key   = (const float*)d_in[1];
    const float* value = (const float*)d_in[2];
    const float* mask  = (const float*)d_in[3];
    const float* wq = (const float*)d_in[4];
    const float* bq = (const float*)d_in[5];
    const float* wk = (const float*)d_in[6];
    const float* bk = (const float*)d_in[7];
    const float* wv = (const float*)d_in[8];
    const float* bv = (const float*)d_in[9];
    const float* wo = (const float*)d_in[10];
    const float* bo = (const float*)d_in[11];
    const float* ln_mha_g = (const float*)d_in[12];
    const float* ln_mha_b = (const float*)d_in[13];
    const float* w1 = (const float*)d_in[14];
    const float* b1 = (const float*)d_in[15];
    const float* w2 = (const float*)d_in[16];
    const float* b2 = (const float*)d_in[17];
    const float* ln_attn_g = (const float*)d_in[18];
    const float* ln_attn_b = (const float*)d_in[19];
    const float* ln_ffn_g = (const float*)d_in[20];
    const float* ln_ffn_b = (const float*)d_in[21];
    (void)in_sizes; (void)n_in;

    float* out = (float*)d_out;

    __half *qh, *kh, *vh, *Qh, *Kp, *Vp, *Vtp, *cth, *aoh, *Fh, *Ph, *WTp;
    float *S, *X, *ao, *Z;
    cudaGetSymbolAddress((void**)&qh, g_qh);
    cudaGetSymbolAddress((void**)&kh, g_kh);
    cudaGetSymbolAddress((void**)&vh, g_vh);
    cudaGetSymbolAddress((void**)&Qh, g_Qh);
    cudaGetSymbolAddress((void**)&Kp, g_Kp);
    cudaGetSymbolAddress((void**)&Vp, g_Vp);
    cudaGetSymbolAddress((void**)&Vtp, g_Vtp);
    cudaGetSymbolAddress((void**)&cth, g_cth);
    cudaGetSymbolAddress((void**)&aoh, g_aoh);
    cudaGetSymbolAddress((void**)&Fh, g_Fh);
    cudaGetSymbolAddress((void**)&Ph, g_Ph);
    cudaGetSymbolAddress((void**)&WTp, g_WTp);
    cudaGetSymbolAddress((void**)&S, g_S);
    cudaGetSymbolAddress((void**)&X, g_X);
    cudaGetSymbolAddress((void**)&ao, g_ao);
    cudaGetSymbolAddress((void**)&Z, g_Z);

    const size_t nMD = (size_t)Mm * Dd;
    const size_t nS  = (size_t)Bb * Hh * Ss * Ss;
    const size_t nVt = (size_t)Bb * Hh * HDIM * Ss;

    __half *KpH = Kp, *KpL = Kp + nMD;
    __half *VpH = Vp, *VpL = Vp + nMD;
    __half *VtH = Vtp, *VtL = Vtp + nVt;

    const size_t wsz = (size_t)4 * Dd * Dd + (size_t)Dd * Ff + (size_t)Ff * Dd;
    __half* WTh = WTp;          __half* WTl = WTp + wsz;
    __half *wqTH = WTh,                      *wqTL = WTl;
    __half *wkTH = WTh + (size_t)Dd * Dd,    *wkTL = WTl + (size_t)Dd * Dd;
    __half *wvTH = WTh + (size_t)2 * Dd * Dd,*wvTL = WTl + (size_t)2 * Dd * Dd;
    __half *woTH = WTh + (size_t)3 * Dd * Dd,*woTL = WTl + (size_t)3 * Dd * Dd;
    __half *w1TH = WTh + (size_t)4 * Dd * Dd,*w1TL = WTl + (size_t)4 * Dd * Dd;
    __half *w2TH = w1TH + (size_t)Dd * Ff,   *w2TL = w1TL + (size_t)Dd * Ff;

    const long long main_elems = (long long)Mm * Dd;
    const long long attn_elems = (long long)nS;
    float* attn_ext = ((long long)out_size >= main_elems + attn_elems)
                          ? (out + main_elems) : nullptr;

    // BN=128: stage = 10240 + 128*160 = 30720 ; 2 stages = 61440 (2 CTAs/SM)
    const int DSZ128 = 2 * (10240 + 128 * 160);
    const int DSZ64  = 2 * (10240 + 64 * 160);
    cudaFuncSetAttribute(gemm_ps<128,0,2>, cudaFuncAttributeMaxDynamicSharedMemorySize, DSZ128);
    cudaFuncSetAttribute(gemm_ps<128,0,1>, cudaFuncAttributeMaxDynamicSharedMemorySize, DSZ128);
    cudaFuncSetAttribute(gemm_ps<128,0,0>, cudaFuncAttributeMaxDynamicSharedMemorySize, DSZ128);
    cudaFuncSetAttribute(gemm_ps<128,1,2>, cudaFuncAttributeMaxDynamicSharedMemorySize, DSZ128);
    cudaFuncSetAttribute(gemm_ps<128,2,0>, cudaFuncAttributeMaxDynamicSharedMemorySize, DSZ128);
    cudaFuncSetAttribute(gemm_ps<64,3,2>,  cudaFuncAttributeMaxDynamicSharedMemorySize, DSZ64);

    dim3 tblk(32, 8);

    convert_f16<<<nMD / 1024, 256>>>(query, qh);
    convert_f16<<<nMD / 1024, 256>>>(key,   kh);
    convert_f16<<<nMD / 1024, 256>>>(value, vh);
    transpose_split<<<dim3(Dd/32, Dd/32), tblk>>>(wq, wqTH, wqTL, Dd, Dd);
    transpose_split<<<dim3(Dd/32, Dd/32), tblk>>>(wk, wkTH, wkTL, Dd, Dd);
    transpose_split<<<dim3(Dd/32, Dd/32), tblk>>>(wv, wvTH, wvTL, Dd, Dd);
    transpose_split<<<dim3(Dd/32, Dd/32), tblk>>>(wo, woTH, woTL, Dd, Dd);
    transpose_split<<<dim3(Ff/32, Dd/32), tblk>>>(w1, w1TH, w1TL, Dd, Ff);
    transpose_split<<<dim3(Dd/32, Ff/32), tblk>>>(w2, w2TH, w2TL, Ff, Dd);

    // QKV projections
    gemm_ps<128,0,2><<<dim3(Dd/128, Mm/128, 1), 256, DSZ128>>>(
        qh, Dd, 0, 0, wqTH, wqTL, Dd, 0, 0,
        nullptr, Qh, nullptr, Dd, 0, 0, bq, Dd);
    gemm_ps<128,0,1><<<dim3(Dd/128, Mm/128, 1), 256, DSZ128>>>(
        kh, Dd, 0, 0, wkTH, wkTL, Dd, 0, 0,
        nullptr, KpH, KpL, Dd, 0, 0, bk, Dd);
    gemm_ps<128,0,1><<<dim3(Dd/128, Mm/128, 1), 256, DSZ128>>>(
        vh, Dd, 0, 0, wvTH, wvTL, Dd, 0, 0,
        nullptr, VpH, VpL, Dd, 0, 0, bv, Dd);

    // V^T per head (pairs)
    vt_pairs<<<dim3(Ss/32, HDIM/32, Bb*Hh), tblk>>>(VpH, VpL, VtH, VtL);

    // scores = QK^T/8 + mask -> fp32 S  (A = Q single, B = K pair)
    gemm_ps<128,2,0><<<dim3(Ss/128, Ss/128, Bb*Hh), 256, DSZ128>>>(
        Qh, Dd, (long long)Ss*Dd, HDIM,
        KpH, KpL, Dd, (long long)Ss*Dd, HDIM,
        S, nullptr, nullptr, Ss, 16LL*Ss*Ss, (long long)Ss*Ss,
        mask, HDIM);

    // softmax -> attn_weights mirror + single-plane fp16 P
    softmax_kernel<<<Bb*Hh*Ss, 256>>>(S, attn_ext, Ph);

    // context = P @ V -> single fp16
    gemm_ps<64,3,2><<<dim3(1, Ss/128, Bb*Hh), 256, DSZ64>>>(
        Ph, Ss, 16LL*Ss*Ss, (long long)Ss*Ss,
        VtH, VtL, Ss, 16LL*HDIM*Ss, (long long)HDIM*Ss,
        nullptr, cth, nullptr, Dd, (long long)Ss*Dd, HDIM,
        nullptr, Ss);

    // O-projection -> fp32 X
    gemm_ps<128,0,0><<<dim3(Dd/128, Mm/128, 1), 256, DSZ128>>>(
        cth, Dd, 0, 0, woTH, woTL, Dd, 0, 0,
        X, nullptr, nullptr, Dd, 0, 0, bo, Dd);

    // Double LayerNorm -> attn_out fp32 + single fp16
    ln_a_kernel<<<Mm, 256>>>(X, query, ln_mha_g, ln_mha_b,
                             ln_attn_g, ln_attn_b, ao, aoh);

    // FFN1 -> single fp16 (relu)
    gemm_ps<128,1,2><<<dim3(Ff/128, Mm/128, 1), 256, DSZ128>>>(
        aoh, Dd, 0, 0, w1TH, w1TL, Dd, 0, 0,
        nullptr, Fh, nullptr, Ff, 0, 0, b1, Dd);

    // FFN2 -> fp32 Z
    gemm_ps<128,0,0><<<dim3(Dd/128, Mm/128, 1), 256, DSZ128>>>(
        Fh, Ff, 0, 0, w2TH, w2TL, Ff, 0, 0,
        Z, nullptr, nullptr, Dd, 0, 0, b2, Ff);

    // Final LayerNorm -> main output
    ln_b_kernel<<<Mm, 256>>>(Z, ao, ln_ffn_g, ln_ffn_b, out);
}

// round 8
// speedup vs baseline: 1.9731x; 1.3967x over previous
#include <cuda_runtime.h>
#include <cuda_fp16.h>
#include <math.h>
#include <stdint.h>

#define Bb 8
#define Ss 1024
#define Dd 1024
#define Hh 16
#define HDIM 64
#define Ff 4096
#define Mm (Bb*Ss)

// ---------------------------------------------------------------------------
// Scratch (device globals). All GEMM operands single-plane fp16.
// ---------------------------------------------------------------------------
__device__ __half g_qh [(size_t)Mm*Dd];            // query fp16
__device__ __half g_kh [(size_t)Mm*Dd];            // key fp16
__device__ __half g_vh [(size_t)Mm*Dd];            // value fp16
__device__ __half g_Qh [(size_t)Mm*Dd];            // Q proj (A of scores)
__device__ __half g_Kh [(size_t)Mm*Dd];            // K proj (B of scores)
__device__ __half g_Vh [(size_t)Mm*Dd];            // V proj
__device__ __half g_Vth[(size_t)Bb*Hh*HDIM*Ss];    // V^T (B of PV)
__device__ __half g_cth[(size_t)Mm*Dd];            // context (A of O-proj)
__device__ __half g_aoh[(size_t)Mm*Dd];            // attn_out (A of FFN1)
__device__ __half g_Fh [(size_t)Mm*Ff];            // FFN mid (A of FFN2)
__device__ __half g_Ph [(size_t)Bb*Hh*Ss*Ss];      // P (A of PV)
__device__ __half g_WT [(size_t)(4*Dd*Dd + Dd*Ff + Ff*Dd)];  // transposed weights
__device__ float  g_S  [(size_t)Bb*Hh*Ss*Ss];
__device__ float  g_X  [(size_t)Mm*Dd];
__device__ float  g_ao [(size_t)Mm*Dd];
__device__ float  g_Z  [(size_t)Mm*Dd];

// ---------------------------------------------------------------------------
// PTX helpers (baseline sm_80+ features, valid on plain sm_103 target)
// ---------------------------------------------------------------------------
__device__ __forceinline__ uint32_t smem_u32(const void* p) {
    uint32_t a;
    asm("{ .reg .u64 t; cvta.to.shared.u64 t, %1; cvt.u32.u64 %0, t; }"
        : "=r"(a) : "l"(p));
    return a;
}
__device__ __forceinline__ void ldsm4(uint32_t& r0, uint32_t& r1, uint32_t& r2,
                                      uint32_t& r3, uint32_t addr) {
    asm volatile("ldmatrix.sync.aligned.m8n8.x4.shared.b16 {%0,%1,%2,%3}, [%4];"
                 : "=r"(r0), "=r"(r1), "=r"(r2), "=r"(r3) : "r"(addr));
}
__device__ __forceinline__ void mma16816(float* d, const uint32_t* a,
                                         const uint32_t* b) {
    asm volatile(
        "mma.sync.aligned.m16n8k16.row.col.f32.f16.f16.f32 "
        "{%0,%1,%2,%3}, {%4,%5,%6,%7}, {%8,%9}, {%0,%1,%2,%3};"
        : "+f"(d[0]), "+f"(d[1]), "+f"(d[2]), "+f"(d[3])
        : "r"(a[0]), "r"(a[1]), "r"(a[2]), "r"(a[3]), "r"(b[0]), "r"(b[1]));
}
__device__ __forceinline__ void cpa16(uint32_t dst, const void* src) {
    asm volatile("cp.async.cg.shared.global [%0], [%1], 16;"
                 :: "r"(dst), "l"(src) : "memory");
}
#define CP_COMMIT() asm volatile("cp.async.commit_group;" ::: "memory")
#define CP_WAIT0()  asm volatile("cp.async.wait_group 0;" ::: "memory")

// ---------------------------------------------------------------------------
// GEMM: C[128 x BN] = A[128,K] @ B[BN,K]^T, fp32 accum, fp16 operands.
//   1 MMA per fragment. 2-stage cp.async pipeline, 2 CTAs/SM.
//   Warp grid 2(m) x 4(n): warp tile 64 x (BN/4).
//   Batch via blockIdx.z: off = (z>>4)*s1 + (z&15)*s2 (elements).
//   EPI: 0=+bias  1=+bias,relu  2=scores(x/8+(1-mask)*-1e4)  3=plain
//   CFMT: 0 = fp32 out (C) ; 2 = fp16 out (CH)
// ---------------------------------------------------------------------------
template<int BN, int EPI, int CFMT>
__global__ void __launch_bounds__(256, 2) gemm_ps(
    const __half* __restrict__ AH,
    long long lda, long long a1, long long a2,
    const __half* __restrict__ BH,
    long long ldb, long long b1, long long b2,
    float* __restrict__ C, __half* __restrict__ CH,
    long long ldc, long long c1, long long c2,
    const float* __restrict__ aux, int K)
{
    constexpr int MF = 4;                 // m16 frags per warp (m span 64)
    constexpr int NF = BN / 32;           // n8 frags per warp (n span BN/4)
    constexpr int NBI = BN / 64;          // B cp.async iters
    constexpr int ABYTES = 10240;
    constexpr int STAGE = ABYTES + BN * 80;

    extern __shared__ char dsm[];

    const int tid = threadIdx.x, lane = tid & 31, wid = tid >> 5;
    const int zb = blockIdx.z >> 4, zh = blockIdx.z & 15;
    const int row0 = blockIdx.y * 128, col0 = blockIdx.x * BN;
    const int m0w = (wid >> 2) * 64, n0w = (wid & 3) * (BN / 4);

    const __half* Abh = AH + zb * a1 + zh * a2 + (size_t)row0 * lda;
    const __half* Bbh = BH + zb * b1 + zh * b2 + (size_t)col0 * ldb;
    float* Cb = C + zb * c1 + zh * c2;
    __half* CbH = CH + zb * c1 + zh * c2;

    const uint32_t sbase = smem_u32(dsm);

    float acc[MF][NF][4];
#pragma unroll
    for (int i = 0; i < MF; i++)
#pragma unroll
        for (int j = 0; j < NF; j++)
#pragma unroll
            for (int k = 0; k < 4; k++) acc[i][j][k] = 0.f;

    auto issue = [&](int st, int k0) {
        uint32_t base = sbase + st * STAGE;
#pragma unroll
        for (int i = 0; i < 2; i++) {       // A: 128 rows x 4 16B groups
            int q = tid + i * 256;
            int r = q >> 2, g = q & 3;
            cpa16(base + r * 80 + g * 16, Abh + (size_t)r * lda + k0 + g * 8);
        }
#pragma unroll
        for (int i = 0; i < NBI; i++) {     // B: BN rows x 4 groups
            int q = tid + i * 256;
            int r = q >> 2, g = q & 3;
            cpa16(base + ABYTES + r * 80 + g * 16,
                  Bbh + (size_t)r * ldb + k0 + g * 8);
        }
        CP_COMMIT();
    };

    const int NC = K >> 5;
    issue(0, 0);

    for (int c = 0; c < NC; c++) {
        CP_WAIT0();
        __syncthreads();
        if (c + 1 < NC) issue((c + 1) & 1, (c + 1) * 32);

        const uint32_t aAh = sbase + (c & 1) * STAGE;
        const uint32_t aBh = aAh + ABYTES;
#pragma unroll
        for (int kk = 0; kk < 32; kk += 16) {
            uint32_t bh[NF][2];
#pragma unroll
            for (int np = 0; np < NF / 2; np++) {
                uint32_t bo = (uint32_t)((n0w + np * 16 + ((lane >> 4) << 3) +
                                          (lane & 7)) * 40 +
                                         kk + ((lane >> 3) & 1) * 8) * 2;
                ldsm4(bh[2 * np][0], bh[2 * np][1], bh[2 * np + 1][0],
                      bh[2 * np + 1][1], aBh + bo);
            }
#pragma unroll
            for (int mi = 0; mi < MF; mi++) {
                uint32_t ao = (uint32_t)((m0w + mi * 16 + (lane & 15)) * 40 +
                                         kk + ((lane >> 4) << 3)) * 2;
                uint32_t ah[4];
                ldsm4(ah[0], ah[1], ah[2], ah[3], aAh + ao);
#pragma unroll
                for (int ni = 0; ni < NF; ni++)
                    mma16816(acc[mi][ni], ah, bh[ni]);
            }
        }
        __syncthreads();
    }

    // ---- epilogue: fragment-direct ----
#pragma unroll
    for (int ni = 0; ni < NF; ni++) {
        const int col = col0 + n0w + ni * 8 + (lane & 3) * 2;
        float2 e = make_float2(0.f, 0.f);
        if (EPI == 0 || EPI == 1) {
            e = *(const float2*)(aux + col);
        } else if (EPI == 2) {
            float2 m = *(const float2*)(aux + (size_t)zb * Ss + col);
            e.x = (1.f - m.x) * -10000.f;
            e.y = (1.f - m.y) * -10000.f;
        }
#pragma unroll
        for (int mi = 0; mi < MF; mi++) {
            const int r0g = row0 + m0w + mi * 16 + (lane >> 2);
            float* a = acc[mi][ni];
            float2 v0, v1;
            if (EPI == 2) {
                v0 = make_float2(a[0] * 0.125f + e.x, a[1] * 0.125f + e.y);
                v1 = make_float2(a[2] * 0.125f + e.x, a[3] * 0.125f + e.y);
            } else {
                v0 = make_float2(a[0] + e.x, a[1] + e.y);
                v1 = make_float2(a[2] + e.x, a[3] + e.y);
                if (EPI == 1) {
                    v0.x = fmaxf(v0.x, 0.f); v0.y = fmaxf(v0.y, 0.f);
                    v1.x = fmaxf(v1.x, 0.f); v1.y = fmaxf(v1.y, 0.f);
                }
            }
            if (CFMT == 0) {
                *(float2*)(Cb + (size_t)r0g * ldc + col) = v0;
                *(float2*)(Cb + (size_t)(r0g + 8) * ldc + col) = v1;
            } else {
                *(__half2*)(CbH + (size_t)r0g * ldc + col) =
                    __floats2half2_rn(v0.x, v0.y);
                *(__half2*)(CbH + (size_t)(r0g + 8) * ldc + col) =
                    __floats2half2_rn(v1.x, v1.y);
            }
        }
    }
}

// ---------------------------------------------------------------------------
// Convert fp32 tensor to fp16
// ---------------------------------------------------------------------------
__global__ void __launch_bounds__(256) convert_f16(
    const float* __restrict__ X, __half* __restrict__ H)
{
    size_t i = (size_t)blockIdx.x * 256 + threadIdx.x;
    float4 v = ((const float4*)X)[i];
    *(__half2*)(H + i * 4)     = __floats2half2_rn(v.x, v.y);
    *(__half2*)(H + i * 4 + 2) = __floats2half2_rn(v.z, v.w);
}

// Weight transpose to fp16: T[c][r] = f16(W[r][c])
__global__ void transpose_f16(const float* __restrict__ W,
                              __half* __restrict__ TH, int R, int C)
{
    __shared__ float t[32][33];
    int c0 = blockIdx.x * 32, r0 = blockIdx.y * 32;
#pragma unroll
    for (int i = threadIdx.y; i < 32; i += 8)
        t[i][threadIdx.x] = W[(size_t)(r0 + i) * C + c0 + threadIdx.x];
    __syncthreads();
#pragma unroll
    for (int i = threadIdx.y; i < 32; i += 8)
        TH[(size_t)(c0 + i) * R + r0 + threadIdx.x] =
            __float2half_rn(t[threadIdx.x][i]);
}

// V^T per (b,h): Vt[bh][d][sk] = V[b][sk][h*64+d]
__global__ void vt_f16(const __half* __restrict__ VH, __half* __restrict__ TH)
{
    __shared__ __half t[32][33];
    const int bh = blockIdx.z, b = bh >> 4, h = bh & 15;
    const int sk0 = blockIdx.x * 32, d0 = blockIdx.y * 32;
    const __half* vh = VH + (size_t)b * Ss * Dd + h * HDIM;
#pragma unroll
    for (int i = threadIdx.y; i < 32; i += 8)
        t[i][threadIdx.x] = vh[(size_t)(sk0 + i) * Dd + d0 + threadIdx.x];
    __syncthreads();
    __half* oh = TH + (size_t)bh * HDIM * Ss;
#pragma unroll
    for (int i = threadIdx.y; i < 32; i += 8)
        oh[(size_t)(d0 + i) * Ss + sk0 + threadIdx.x] = t[threadIdx.x][i];
}

// ---------------------------------------------------------------------------
// Softmax over rows of 1024: fp32 mirror (attn_weights) + fp16 P plane
// ---------------------------------------------------------------------------
__global__ void __launch_bounds__(256) softmax_kernel(
    const float* __restrict__ S, float* __restrict__ ext,
    __half* __restrict__ PH)
{
    __shared__ float sbuf[8];
    const size_t row = blockIdx.x;
    const float* p = S + row * Ss;
    const int tid = threadIdx.x;
    const int lane = tid & 31, w = tid >> 5;

    float4 x = *(const float4*)(p + tid * 4);
    float m = fmaxf(fmaxf(x.x, x.y), fmaxf(x.z, x.w));
#pragma unroll
    for (int o = 16; o > 0; o >>= 1) m = fmaxf(m, __shfl_xor_sync(~0u, m, o));
    if (lane == 0) sbuf[w] = m;
    __syncthreads();
    m = sbuf[0];
#pragma unroll
    for (int i = 1; i < 8; i++) m = fmaxf(m, sbuf[i]);

    float4 e;
    e.x = expf(x.x - m); e.y = expf(x.y - m);
    e.z = expf(x.z - m); e.w = expf(x.w - m);
    float s = e.x + e.y + e.z + e.w;
#pragma unroll
    for (int o = 16; o > 0; o >>= 1) s += __shfl_xor_sync(~0u, s, o);
    __syncthreads();
    if (lane == 0) sbuf[w] = s;
    __syncthreads();
    s = 0.f;
#pragma unroll
    for (int i = 0; i < 8; i++) s += sbuf[i];
    float inv = 1.0f / s;
    e.x *= inv; e.y *= inv; e.z *= inv; e.w *= inv;
    if (ext) *(float4*)(ext + row * Ss + tid * 4) = e;
    *(__half2*)(PH + row * Ss + tid * 4)     = __floats2half2_rn(e.x, e.y);
    *(__half2*)(PH + row * Ss + tid * 4 + 2) = __floats2half2_rn(e.z, e.w);
}

// ---------------------------------------------------------------------------
// LayerNorm kernels
// ---------------------------------------------------------------------------
__device__ __forceinline__ float block_sum(float v, float* sbuf) {
    const int lane = threadIdx.x & 31, w = threadIdx.x >> 5;
#pragma unroll
    for (int o = 16; o > 0; o >>= 1) v += __shfl_xor_sync(~0u, v, o);
    __syncthreads();
    if (lane == 0) sbuf[w] = v;
    __syncthreads();
    float s = 0.f;
#pragma unroll
    for (int i = 0; i < 8; i++) s += sbuf[i];
    return s;
}

// t = X + q ; ln1 = LN(t,1e-8) ; t2 = q + ln1 ; out = LN(t2,1e-6)
__global__ void __launch_bounds__(256) ln_a_kernel(
    const float* __restrict__ X, const float* __restrict__ q,
    const float* __restrict__ g1, const float* __restrict__ b1,
    const float* __restrict__ g2, const float* __restrict__ b2,
    float* __restrict__ out, __half* __restrict__ OH)
{
    __shared__ float sbuf[8];
    const size_t row = blockIdx.x;
    const int col = threadIdx.x * 4;
    float4 xv = *(const float4*)(X + row * Dd + col);
    float4 qv = *(const float4*)(q + row * Dd + col);
    float t[4] = { xv.x + qv.x, xv.y + qv.y, xv.z + qv.z, xv.w + qv.w };

    float mu = block_sum(t[0] + t[1] + t[2] + t[3], sbuf) * (1.0f / Dd);
    float ss = 0.f;
#pragma unroll
    for (int i = 0; i < 4; i++) { float d = t[i] - mu; ss += d * d; }
    float var = block_sum(ss, sbuf) * (1.0f / Dd);
    float inv = rsqrtf(var + 1e-8f);

    float4 g = *(const float4*)(g1 + col);
    float4 be = *(const float4*)(b1 + col);
    float qarr[4] = { qv.x, qv.y, qv.z, qv.w };
    float garr[4] = { g.x, g.y, g.z, g.w };
    float barr[4] = { be.x, be.y, be.z, be.w };
    float t2[4];
#pragma unroll
    for (int i = 0; i < 4; i++)
        t2[i] = qarr[i] + (t[i] - mu) * inv * garr[i] + barr[i];

    float mu2 = block_sum(t2[0] + t2[1] + t2[2] + t2[3], sbuf) * (1.0f / Dd);
    float ss2 = 0.f;
#pragma unroll
    for (int i = 0; i < 4; i++) { float d = t2[i] - mu2; ss2 += d * d; }
    float var2 = block_sum(ss2, sbuf) * (1.0f / Dd);
    float inv2 = rsqrtf(var2 + 1e-6f);

    g = *(const float4*)(g2 + col);
    be = *(const float4*)(b2 + col);
    float4 o;
    o.x = (t2[0] - mu2) * inv2 * g.x + be.x;
    o.y = (t2[1] - mu2) * inv2 * g.y + be.y;
    o.z = (t2[2] - mu2) * inv2 * g.z + be.z;
    o.w = (t2[3] - mu2) * inv2 * g.w + be.w;
    *(float4*)(out + row * Dd + col) = o;
    *(__half2*)(OH + row * Dd + col)     = __floats2half2_rn(o.x, o.y);
    *(__half2*)(OH + row * Dd + col + 2) = __floats2half2_rn(o.z, o.w);
}

__global__ void __launch_bounds__(256) ln_b_kernel(
    const float* __restrict__ Z, const float* __restrict__ res,
    const float* __restrict__ g1, const float* __restrict__ b1,
    float* __restrict__ out)
{
    __shared__ float sbuf[8];
    const size_t row = blockIdx.x;
    const int col = threadIdx.x * 4;
    float4 zv = *(const float4*)(Z + row * Dd + col);
    float4 rv = *(const float4*)(res + row * Dd + col);
    float t[4] = { zv.x + rv.x, zv.y + rv.y, zv.z + rv.z, zv.w + rv.w };

    float mu = block_sum(t[0] + t[1] + t[2] + t[3], sbuf) * (1.0f / Dd);
    float ss = 0.f;
#pragma unroll
    for (int i = 0; i < 4; i++) { float d = t[i] - mu; ss += d * d; }
    float var = block_sum(ss, sbuf) * (1.0f / Dd);
    float inv = rsqrtf(var + 1e-6f);

    float4 g = *(const float4*)(g1 + col);
    float4 be = *(const float4*)(b1 + col);
    float4 o;
    o.x = (t[0] - mu) * inv * g.x + be.x;
    o.y = (t[1] - mu) * inv * g.y + be.y;
    o.z = (t[2] - mu) * inv * g.z + be.z;
    o.w = (t[3] - mu) * inv * g.w + be.w;
    *(float4*)(out + row * Dd + col) = o;
}

// ---------------------------------------------------------------------------
// kernel_launch
// ---------------------------------------------------------------------------
extern "C" void kernel_launch(void* const* d_in, const int* in_sizes, int n_in,
                              void* d_out, int out_size)
{
    const float* query = (const float*)d_in[0];
    const float* key   = (const float*)d_in[1];
    const float* value = (const float*)d_in[2];
    const float* mask  = (const float*)d_in[3];
    const float* wq = (const float*)d_in[4];
    const float* bq = (const float*)d_in[5];
    const float* wk = (const float*)d_in[6];
    const float* bk = (const float*)d_in[7];
    const float* wv = (const float*)d_in[8];
    const float* bv = (const float*)d_in[9];
    const float* wo = (const float*)d_in[10];
    const float* bo = (const float*)d_in[11];
    const float* ln_mha_g = (const float*)d_in[12];
    const float* ln_mha_b = (const float*)d_in[13];
    const float* w1 = (const float*)d_in[14];
    const float* b1 = (const float*)d_in[15];
    const float* w2 = (const float*)d_in[16];
    const float* b2 = (const float*)d_in[17];
    const float* ln_attn_g = (const float*)d_in[18];
    const float* ln_attn_b = (const float*)d_in[19];
    const float* ln_ffn_g = (const float*)d_in[20];
    const float* ln_ffn_b = (const float*)d_in[21];
    (void)in_sizes; (void)n_in;

    float* out = (float*)d_out;

    __half *qh, *kh, *vh, *Qh, *Kh, *Vh, *Vth, *cth, *aoh, *Fh, *Ph, *WT;
    float *S, *X, *ao, *Z;
    cudaGetSymbolAddress((void**)&qh, g_qh);
    cudaGetSymbolAddress((void**)&kh, g_kh);
    cudaGetSymbolAddress((void**)&vh, g_vh);
    cudaGetSymbolAddress((void**)&Qh, g_Qh);
    cudaGetSymbolAddress((void**)&Kh, g_Kh);
    cudaGetSymbolAddress((void**)&Vh, g_Vh);
    cudaGetSymbolAddress((void**)&Vth, g_Vth);
    cudaGetSymbolAddress((void**)&cth, g_cth);
    cudaGetSymbolAddress((void**)&aoh, g_aoh);
    cudaGetSymbolAddress((void**)&Fh, g_Fh);
    cudaGetSymbolAddress((void**)&Ph, g_Ph);
    cudaGetSymbolAddress((void**)&WT, g_WT);
    cudaGetSymbolAddress((void**)&S, g_S);
    cudaGetSymbolAddress((void**)&X, g_X);
    cudaGetSymbolAddress((void**)&ao, g_ao);
    cudaGetSymbolAddress((void**)&Z, g_Z);

    const size_t nMD = (size_t)Mm * Dd;
    const size_t nS  = (size_t)Bb * Hh * Ss * Ss;

    __half *wqT = WT;
    __half *wkT = WT + (size_t)Dd * Dd;
    __half *wvT = WT + (size_t)2 * Dd * Dd;
    __half *woT = WT + (size_t)3 * Dd * Dd;
    __half *w1T = WT + (size_t)4 * Dd * Dd;              // [F, D]
    __half *w2T = w1T + (size_t)Dd * Ff;                 // [D, F]

    const long long main_elems = (long long)Mm * Dd;
    const long long attn_elems = (long long)nS;
    float* attn_ext = ((long long)out_size >= main_elems + attn_elems)
                          ? (out + main_elems) : nullptr;

    // BN=128: stage = 10240 + 128*80 = 20480 ; 2 stages = 40960 (2 CTAs/SM)
    const int DSZ128 = 2 * (10240 + 128 * 80);
    const int DSZ64  = 2 * (10240 + 64 * 80);
    cudaFuncSetAttribute(gemm_ps<128,0,2>, cudaFuncAttributeMaxDynamicSharedMemorySize, DSZ128);
    cudaFuncSetAttribute(gemm_ps<128,0,0>, cudaFuncAttributeMaxDynamicSharedMemorySize, DSZ128);
    cudaFuncSetAttribute(gemm_ps<128,1,2>, cudaFuncAttributeMaxDynamicSharedMemorySize, DSZ128);
    cudaFuncSetAttribute(gemm_ps<128,2,0>, cudaFuncAttributeMaxDynamicSharedMemorySize, DSZ128);
    cudaFuncSetAttribute(gemm_ps<64,3,2>,  cudaFuncAttributeMaxDynamicSharedMemorySize, DSZ64);

    dim3 tblk(32, 8);

    convert_f16<<<nMD / 1024, 256>>>(query, qh);
    convert_f16<<<nMD / 1024, 256>>>(key,   kh);
    convert_f16<<<nMD / 1024, 256>>>(value, vh);
    transpose_f16<<<dim3(Dd/32, Dd/32), tblk>>>(wq, wqT, Dd, Dd);
    transpose_f16<<<dim3(Dd/32, Dd/32), tblk>>>(wk, wkT, Dd, Dd);
    transpose_f16<<<dim3(Dd/32, Dd/32), tblk>>>(wv, wvT, Dd, Dd);
    transpose_f16<<<dim3(Dd/32, Dd/32), tblk>>>(wo, woT, Dd, Dd);
    transpose_f16<<<dim3(Ff/32, Dd/32), tblk>>>(w1, w1T, Dd, Ff);
    transpose_f16<<<dim3(Dd/32, Ff/32), tblk>>>(w2, w2T, Ff, Dd);

    // QKV projections -> fp16
    gemm_ps<128,0,2><<<dim3(Dd/128, Mm/128, 1), 256, DSZ128>>>(
        qh, Dd, 0, 0, wqT, Dd, 0, 0,
        nullptr, Qh, Dd, 0, 0, bq, Dd);
    gemm_ps<128,0,2><<<dim3(Dd/128, Mm/128, 1), 256, DSZ128>>>(
        kh, Dd, 0, 0, wkT, Dd, 0, 0,
        nullptr, Kh, Dd, 0, 0, bk, Dd);
    gemm_ps<128,0,2><<<dim3(Dd/128, Mm/128, 1), 256, DSZ128>>>(
        vh, Dd, 0, 0, wvT, Dd, 0, 0,
        nullptr, Vh, Dd, 0, 0, bv, Dd);

    // V^T per head
    vt_f16<<<dim3(Ss/32, HDIM/32, Bb*Hh), tblk>>>(Vh, Vth);

    // scores = QK^T/8 + mask -> fp32 S
    gemm_ps<128,2,0><<<dim3(Ss/128, Ss/128, Bb*Hh), 256, DSZ128>>>(
        Qh, Dd, (long long)Ss*Dd, HDIM,
        Kh, Dd, (long long)Ss*Dd, HDIM,
        S, nullptr, Ss, 16LL*Ss*Ss, (long long)Ss*Ss,
        mask, HDIM);

    // softmax -> attn_weights mirror + fp16 P
    softmax_kernel<<<Bb*Hh*Ss, 256>>>(S, attn_ext, Ph);

    // context = P @ V -> fp16
    gemm_ps<64,3,2><<<dim3(1, Ss/128, Bb*Hh), 256, DSZ64>>>(
        Ph, Ss, 16LL*Ss*Ss, (long long)Ss*Ss,
        Vth, Ss, 16LL*HDIM*Ss, (long long)HDIM*Ss,
        nullptr, cth, Dd, (long long)Ss*Dd, HDIM,
        nullptr, Ss);

    // O-projection -> fp32 X
    gemm_ps<128,0,0><<<dim3(Dd/128, Mm/128, 1), 256, DSZ128>>>(
        cth, Dd, 0, 0, woT, Dd, 0, 0,
        X, nullptr, Dd, 0, 0, bo, Dd);

    // Double LayerNorm -> attn_out fp32 + fp16
    ln_a_kernel<<<Mm, 256>>>(X, query, ln_mha_g, ln_mha_b,
                             ln_attn_g, ln_attn_b, ao, aoh);

    // FFN1 -> fp16 (relu)
    gemm_ps<128,1,2><<<dim3(Ff/128, Mm/128, 1), 256, DSZ128>>>(
        aoh, Dd, 0, 0, w1T, Dd, 0, 0,
        nullptr, Fh, Ff, 0, 0, b1, Dd);

    // FFN2 -> fp32 Z
    gemm_ps<128,0,0><<<dim3(Dd/128, Mm/128, 1), 256, DSZ128>>>(
        Fh, Ff, 0, 0, w2T, Ff, 0, 0,
        Z, nullptr, Dd, 0, 0, b2, Ff);

    // Final LayerNorm -> main output
    ln_b_kernel<<<Mm, 256>>>(Z, ao, ln_ffn_g, ln_ffn_b, out);
}

// round 9
// speedup vs baseline: 2.0452x; 1.0365x over previous
#include <cuda_runtime.h>
#include <cuda_fp16.h>
#include <math.h>
#include <stdint.h>

#define Bb 8
#define Ss 1024
#define Dd 1024
#define Hh 16
#define HDIM 64
#define Ff 4096
#define Mm (Bb*Ss)

// ---------------------------------------------------------------------------
// Scratch (device globals). All GEMM operands single-plane fp16.
// ---------------------------------------------------------------------------
__device__ __half g_qh [(size_t)Mm*Dd];
__device__ __half g_kh [(size_t)Mm*Dd];
__device__ __half g_vh [(size_t)Mm*Dd];
__device__ __half g_Qh [(size_t)Mm*Dd];
__device__ __half g_Kh [(size_t)Mm*Dd];
__device__ __half g_Vh [(size_t)Mm*Dd];
__device__ __half g_Vth[(size_t)Bb*Hh*HDIM*Ss];
__device__ __half g_cth[(size_t)Mm*Dd];
__device__ __half g_aoh[(size_t)Mm*Dd];
__device__ __half g_Fh [(size_t)Mm*Ff];
__device__ __half g_Ph [(size_t)Bb*Hh*Ss*Ss];
__device__ __half g_Sh [(size_t)Bb*Hh*Ss*Ss];      // scores fp16
__device__ __half g_WT [(size_t)(4*Dd*Dd + Dd*Ff + Ff*Dd)];
__device__ float  g_X  [(size_t)Mm*Dd];
__device__ float  g_ao [(size_t)Mm*Dd];
__device__ float  g_Z  [(size_t)Mm*Dd];

// ---------------------------------------------------------------------------
// PTX helpers
// ---------------------------------------------------------------------------
__device__ __forceinline__ uint32_t smem_u32(const void* p) {
    uint32_t a;
    asm("{ .reg .u64 t; cvta.to.shared.u64 t, %1; cvt.u32.u64 %0, t; }"
        : "=r"(a) : "l"(p));
    return a;
}
__device__ __forceinline__ void ldsm4(uint32_t& r0, uint32_t& r1, uint32_t& r2,
                                      uint32_t& r3, uint32_t addr) {
    asm volatile("ldmatrix.sync.aligned.m8n8.x4.shared.b16 {%0,%1,%2,%3}, [%4];"
                 : "=r"(r0), "=r"(r1), "=r"(r2), "=r"(r3) : "r"(addr));
}
__device__ __forceinline__ void mma16816(float* d, const uint32_t* a,
                                         const uint32_t* b) {
    asm volatile(
        "mma.sync.aligned.m16n8k16.row.col.f32.f16.f16.f32 "
        "{%0,%1,%2,%3}, {%4,%5,%6,%7}, {%8,%9}, {%0,%1,%2,%3};"
        : "+f"(d[0]), "+f"(d[1]), "+f"(d[2]), "+f"(d[3])
        : "r"(a[0]), "r"(a[1]), "r"(a[2]), "r"(a[3]), "r"(b[0]), "r"(b[1]));
}
__device__ __forceinline__ void cpa16(uint32_t dst, const void* src) {
    asm volatile("cp.async.cg.shared.global [%0], [%1], 16;"
                 :: "r"(dst), "l"(src) : "memory");
}
#define CP_COMMIT() asm volatile("cp.async.commit_group;" ::: "memory")
#define CP_WAIT0()  asm volatile("cp.async.wait_group 0;" ::: "memory")
#define CP_WAIT1()  asm volatile("cp.async.wait_group 1;" ::: "memory")

// ---------------------------------------------------------------------------
// GEMM: C[128 x BN] = A[128,K] @ B[BN,K]^T, fp32 accum, fp16 operands.
//   1 MMA per fragment. 3-stage cp.async pipeline (wait_group 1), 2 CTAs/SM.
//   Warp grid 2(m) x 4(n). Batch via blockIdx.z.
//   EPI: 0=+bias  1=+bias,relu  2=scores(x/8+(1-mask)*-1e4)  3=plain
//   CFMT: 0 = fp32 out (C) ; 2 = fp16 out (CH)
// ---------------------------------------------------------------------------
template<int BN, int EPI, int CFMT>
__global__ void __launch_bounds__(256, 2) gemm_ps(
    const __half* __restrict__ AH,
    long long lda, long long a1, long long a2,
    const __half* __restrict__ BH,
    long long ldb, long long b1, long long b2,
    float* __restrict__ C, __half* __restrict__ CH,
    long long ldc, long long c1, long long c2,
    const float* __restrict__ aux, int K)
{
    constexpr int MF = 4;
    constexpr int NF = BN / 32;
    constexpr int NBI = BN / 64;
    constexpr int ABYTES = 10240;
    constexpr int STAGE = ABYTES + BN * 80;

    extern __shared__ char dsm[];

    const int tid = threadIdx.x, lane = tid & 31, wid = tid >> 5;
    const int zb = blockIdx.z >> 4, zh = blockIdx.z & 15;
    const int row0 = blockIdx.y * 128, col0 = blockIdx.x * BN;
    const int m0w = (wid >> 2) * 64, n0w = (wid & 3) * (BN / 4);

    const __half* Abh = AH + zb * a1 + zh * a2 + (size_t)row0 * lda;
    const __half* Bbh = BH + zb * b1 + zh * b2 + (size_t)col0 * ldb;
    float* Cb = C + zb * c1 + zh * c2;
    __half* CbH = CH + zb * c1 + zh * c2;

    const uint32_t sbase = smem_u32(dsm);

    float acc[MF][NF][4];
#pragma unroll
    for (int i = 0; i < MF; i++)
#pragma unroll
        for (int j = 0; j < NF; j++)
#pragma unroll
            for (int k = 0; k < 4; k++) acc[i][j][k] = 0.f;

    auto issue = [&](int st, int k0) {
        uint32_t base = sbase + st * STAGE;
#pragma unroll
        for (int i = 0; i < 2; i++) {
            int q = tid + i * 256;
            int r = q >> 2, g = q & 3;
            cpa16(base + r * 80 + g * 16, Abh + (size_t)r * lda + k0 + g * 8);
        }
#pragma unroll
        for (int i = 0; i < NBI; i++) {
            int q = tid + i * 256;
            int r = q >> 2, g = q & 3;
            cpa16(base + ABYTES + r * 80 + g * 16,
                  Bbh + (size_t)r * ldb + k0 + g * 8);
        }
        CP_COMMIT();
    };

    const int NC = K >> 5;
    issue(0, 0);
    if (NC > 1) issue(1, 32);

    for (int c = 0; c < NC; c++) {
        if (c + 1 < NC) CP_WAIT1(); else CP_WAIT0();
        __syncthreads();
        if (c + 2 < NC) issue((c + 2) % 3, (c + 2) * 32);

        const uint32_t aAh = sbase + (c % 3) * STAGE;
        const uint32_t aBh = aAh + ABYTES;
#pragma unroll
        for (int kk = 0; kk < 32; kk += 16) {
            uint32_t bh[NF][2];
#pragma unroll
            for (int np = 0; np < NF / 2; np++) {
                uint32_t bo = (uint32_t)((n0w + np * 16 + ((lane >> 4) << 3) +
                                          (lane & 7)) * 40 +
                                         kk + ((lane >> 3) & 1) * 8) * 2;
                ldsm4(bh[2 * np][0], bh[2 * np][1], bh[2 * np + 1][0],
                      bh[2 * np + 1][1], aBh + bo);
            }
#pragma unroll
            for (int mi = 0; mi < MF; mi++) {
                uint32_t ao = (uint32_t)((m0w + mi * 16 + (lane & 15)) * 40 +
                                         kk + ((lane >> 4) << 3)) * 2;
                uint32_t ah[4];
                ldsm4(ah[0], ah[1], ah[2], ah[3], aAh + ao);
#pragma unroll
                for (int ni = 0; ni < NF; ni++)
                    mma16816(acc[mi][ni], ah, bh[ni]);
            }
        }
        __syncthreads();
    }

    // ---- epilogue ----
#pragma unroll
    for (int ni = 0; ni < NF; ni++) {
        const int col = col0 + n0w + ni * 8 + (lane & 3) * 2;
        float2 e = make_float2(0.f, 0.f);
        if (EPI == 0 || EPI == 1) {
            e = *(const float2*)(aux + col);
        } else if (EPI == 2) {
            float2 m = *(const float2*)(aux + (size_t)zb * Ss + col);
            e.x = (1.f - m.x) * -10000.f;
            e.y = (1.f - m.y) * -10000.f;
        }
#pragma unroll
        for (int mi = 0; mi < MF; mi++) {
            const int r0g = row0 + m0w + mi * 16 + (lane >> 2);
            float* a = acc[mi][ni];
            float2 v0, v1;
            if (EPI == 2) {
                v0 = make_float2(a[0] * 0.125f + e.x, a[1] * 0.125f + e.y);
                v1 = make_float2(a[2] * 0.125f + e.x, a[3] * 0.125f + e.y);
            } else {
                v0 = make_float2(a[0] + e.x, a[1] + e.y);
                v1 = make_float2(a[2] + e.x, a[3] + e.y);
                if (EPI == 1) {
                    v0.x = fmaxf(v0.x, 0.f); v0.y = fmaxf(v0.y, 0.f);
                    v1.x = fmaxf(v1.x, 0.f); v1.y = fmaxf(v1.y, 0.f);
                }
            }
            if (CFMT == 0) {
                *(float2*)(Cb + (size_t)r0g * ldc + col) = v0;
                *(float2*)(Cb + (size_t)(r0g + 8) * ldc + col) = v1;
            } else {
                *(__half2*)(CbH + (size_t)r0g * ldc + col) =
                    __floats2half2_rn(v0.x, v0.y);
                *(__half2*)(CbH + (size_t)(r0g + 8) * ldc + col) =
                    __floats2half2_rn(v1.x, v1.y);
            }
        }
    }
}

// ---------------------------------------------------------------------------
// Convert fp32 tensor to fp16
// ---------------------------------------------------------------------------
__global__ void __launch_bounds__(256) convert_f16(
    const float* __restrict__ X, __half* __restrict__ H)
{
    size_t i = (size_t)blockIdx.x * 256 + threadIdx.x;
    float4 v = ((const float4*)X)[i];
    *(__half2*)(H + i * 4)     = __floats2half2_rn(v.x, v.y);
    *(__half2*)(H + i * 4 + 2) = __floats2half2_rn(v.z, v.w);
}

// Weight transpose to fp16
__global__ void transpose_f16(const float* __restrict__ W,
                              __half* __restrict__ TH, int R, int C)
{
    __shared__ float t[32][33];
    int c0 = blockIdx.x * 32, r0 = blockIdx.y * 32;
#pragma unroll
    for (int i = threadIdx.y; i < 32; i += 8)
        t[i][threadIdx.x] = W[(size_t)(r0 + i) * C + c0 + threadIdx.x];
    __syncthreads();
#pragma unroll
    for (int i = threadIdx.y; i < 32; i += 8)
        TH[(size_t)(c0 + i) * R + r0 + threadIdx.x] =
            __float2half_rn(t[threadIdx.x][i]);
}

// V^T per (b,h)
__global__ void vt_f16(const __half* __restrict__ VH, __half* __restrict__ TH)
{
    __shared__ __half t[32][33];
    const int bh = blockIdx.z, b = bh >> 4, h = bh & 15;
    const int sk0 = blockIdx.x * 32, d0 = blockIdx.y * 32;
    const __half* vh = VH + (size_t)b * Ss * Dd + h * HDIM;
#pragma unroll
    for (int i = threadIdx.y; i < 32; i += 8)
        t[i][threadIdx.x] = vh[(size_t)(sk0 + i) * Dd + d0 + threadIdx.x];
    __syncthreads();
    __half* oh = TH + (size_t)bh * HDIM * Ss;
#pragma unroll
    for (int i = threadIdx.y; i < 32; i += 8)
        oh[(size_t)(d0 + i) * Ss + sk0 + threadIdx.x] = t[threadIdx.x][i];
}

// ---------------------------------------------------------------------------
// Softmax over rows of 1024: reads fp16 scores, writes fp32 ext + fp16 P
// ---------------------------------------------------------------------------
__global__ void __launch_bounds__(256) softmax_kernel(
    const __half* __restrict__ S, float* __restrict__ ext,
    __half* __restrict__ PH)
{
    __shared__ float sbuf[8];
    const size_t row = blockIdx.x;
    const __half* p = S + row * Ss;
    const int tid = threadIdx.x;
    const int lane = tid & 31, w = tid >> 5;

    __half2 h0 = *(const __half2*)(p + tid * 4);
    __half2 h1 = *(const __half2*)(p + tid * 4 + 2);
    float2 f0 = __half22float2(h0), f1 = __half22float2(h1);
    float4 x = make_float4(f0.x, f0.y, f1.x, f1.y);
    float m = fmaxf(fmaxf(x.x, x.y), fmaxf(x.z, x.w));
#pragma unroll
    for (int o = 16; o > 0; o >>= 1) m = fmaxf(m, __shfl_xor_sync(~0u, m, o));
    if (lane == 0) sbuf[w] = m;
    __syncthreads();
    m = sbuf[0];
#pragma unroll
    for (int i = 1; i < 8; i++) m = fmaxf(m, sbuf[i]);

    float4 e;
    e.x = expf(x.x - m); e.y = expf(x.y - m);
    e.z = expf(x.z - m); e.w = expf(x.w - m);
    float s = e.x + e.y + e.z + e.w;
#pragma unroll
    for (int o = 16; o > 0; o >>= 1) s += __shfl_xor_sync(~0u, s, o);
    __syncthreads();
    if (lane == 0) sbuf[w] = s;
    __syncthreads();
    s = 0.f;
#pragma unroll
    for (int i = 0; i < 8; i++) s += sbuf[i];
    float inv = 1.0f / s;
    e.x *= inv; e.y *= inv; e.z *= inv; e.w *= inv;
    if (ext) *(float4*)(ext + row * Ss + tid * 4) = e;
    *(__half2*)(PH + row * Ss + tid * 4)     = __floats2half2_rn(e.x, e.y);
    *(__half2*)(PH + row * Ss + tid * 4 + 2) = __floats2half2_rn(e.z, e.w);
}

// ---------------------------------------------------------------------------
// LayerNorm kernels
// ---------------------------------------------------------------------------
__device__ __forceinline__ float block_sum(float v, float* sbuf) {
    const int lane = threadIdx.x & 31, w = threadIdx.x >> 5;
#pragma unroll
    for (int o = 16; o > 0; o >>= 1) v += __shfl_xor_sync(~0u, v, o);
    __syncthreads();
    if (lane == 0) sbuf[w] = v;
    __syncthreads();
    float s = 0.f;
#pragma unroll
    for (int i = 0; i < 8; i++) s += sbuf[i];
    return s;
}

__global__ void __launch_bounds__(256) ln_a_kernel(
    const float* __restrict__ X, const float* __restrict__ q,
    const float* __restrict__ g1, const float* __restrict__ b1,
    const float* __restrict__ g2, const float* __restrict__ b2,
    float* __restrict__ out, __half* __restrict__ OH)
{
    __shared__ float sbuf[8];
    const size_t row = blockIdx.x;
    const int col = threadIdx.x * 4;
    float4 xv = *(const float4*)(X + row * Dd + col);
    float4 qv = *(const float4*)(q + row * Dd + col);
    float t[4] = { xv.x + qv.x, xv.y + qv.y, xv.z + qv.z, xv.w + qv.w };

    float mu = block_sum(t[0] + t[1] + t[2] + t[3], sbuf) * (1.0f / Dd);
    float ss = 0.f;
#pragma unroll
    for (int i = 0; i < 4; i++) { float d = t[i] - mu; ss += d * d; }
    float var = block_sum(ss, sbuf) * (1.0f / Dd);
    float inv = rsqrtf(var + 1e-8f);

    float4 g = *(const float4*)(g1 + col);
    float4 be = *(const float4*)(b1 + col);
    float qarr[4] = { qv.x, qv.y, qv.z, qv.w };
    float garr[4] = { g.x, g.y, g.z, g.w };
    float barr[4] = { be.x, be.y, be.z, be.w };
    float t2[4];
#pragma unroll
    for (int i = 0; i < 4; i++)
        t2[i] = qarr[i] + (t[i] - mu) * inv * garr[i] + barr[i];

    float mu2 = block_sum(t2[0] + t2[1] + t2[2] + t2[3], sbuf) * (1.0f / Dd);
    float ss2 = 0.f;
#pragma unroll
    for (int i = 0; i < 4; i++) { float d = t2[i] - mu2; ss2 += d * d; }
    float var2 = block_sum(ss2, sbuf) * (1.0f / Dd);
    float inv2 = rsqrtf(var2 + 1e-6f);

    g = *(const float4*)(g2 + col);
    be = *(const float4*)(b2 + col);
    float4 o;
    o.x = (t2[0] - mu2) * inv2 * g.x + be.x;
    o.y = (t2[1] - mu2) * inv2 * g.y + be.y;
    o.z = (t2[2] - mu2) * inv2 * g.z + be.z;
    o.w = (t2[3] - mu2) * inv2 * g.w + be.w;
    *(float4*)(out + row * Dd + col) = o;
    *(__half2*)(OH + row * Dd + col)     = __floats2half2_rn(o.x, o.y);
    *(__half2*)(OH + row * Dd + col + 2) = __floats2half2_rn(o.z, o.w);
}

__global__ void __launch_bounds__(256) ln_b_kernel(
    const float* __restrict__ Z, const float* __restrict__ res,
    const float* __restrict__ g1, const float* __restrict__ b1,
    float* __restrict__ out)
{
    __shared__ float sbuf[8];
    const size_t row = blockIdx.x;
    const int col = threadIdx.x * 4;
    float4 zv = *(const float4*)(Z + row * Dd + col);
    float4 rv = *(const float4*)(res + row * Dd + col);
    float t[4] = { zv.x + rv.x, zv.y + rv.y, zv.z + rv.z, zv.w + rv.w };

    float mu = block_sum(t[0] + t[1] + t[2] + t[3], sbuf) * (1.0f / Dd);
    float ss = 0.f;
#pragma unroll
    for (int i = 0; i < 4; i++) { float d = t[i] - mu; ss += d * d; }
    float var = block_sum(ss, sbuf) * (1.0f / Dd);
    float inv = rsqrtf(var + 1e-6f);

    float4 g = *(const float4*)(g1 + col);
    float4 be = *(const float4*)(b1 + col);
    float4 o;
    o.x = (t[0] - mu) * inv * g.x + be.x;
    o.y = (t[1] - mu) * inv * g.y + be.y;
    o.z = (t[2] - mu) * inv * g.z + be.z;
    o.w = (t[3] - mu) * inv * g.w + be.w;
    *(float4*)(out + row * Dd + col) = o;
}

// ---------------------------------------------------------------------------
// kernel_launch
// ---------------------------------------------------------------------------
extern "C" void kernel_launch(void* const* d_in, const int* in_sizes, int n_in,
                              void* d_out, int out_size)
{
    const float* query = (const float*)d_in[0];
    const float* key   = (const float*)d_in[1];
    const float* value = (const float*)d_in[2];
    const float* mask  = (const float*)d_in[3];
    const float* wq = (const float*)d_in[4];
    const float* bq = (const float*)d_in[5];
    const float* wk = (const float*)d_in[6];
    const float* bk = (const float*)d_in[7];
    const float* wv = (const float*)d_in[8];
    const float* bv = (const float*)d_in[9];
    const float* wo = (const float*)d_in[10];
    const float* bo = (const float*)d_in[11];
    const float* ln_mha_g = (const float*)d_in[12];
    const float* ln_mha_b = (const float*)d_in[13];
    const float* w1 = (const float*)d_in[14];
    const float* b1 = (const float*)d_in[15];
    const float* w2 = (const float*)d_in[16];
    const float* b2 = (const float*)d_in[17];
    const float* ln_attn_g = (const float*)d_in[18];
    const float* ln_attn_b = (const float*)d_in[19];
    const float* ln_ffn_g = (const float*)d_in[20];
    const float* ln_ffn_b = (const float*)d_in[21];
    (void)in_sizes; (void)n_in;

    float* out = (float*)d_out;

    __half *qh, *kh, *vh, *Qh, *Kh, *Vh, *Vth, *cth, *aoh, *Fh, *Ph, *Sh, *WT;
    float *X, *ao, *Z;
    cudaGetSymbolAddress((void**)&qh, g_qh);
    cudaGetSymbolAddress((void**)&kh, g_kh);
    cudaGetSymbolAddress((void**)&vh, g_vh);
    cudaGetSymbolAddress((void**)&Qh, g_Qh);
    cudaGetSymbolAddress((void**)&Kh, g_Kh);
    cudaGetSymbolAddress((void**)&Vh, g_Vh);
    cudaGetSymbolAddress((void**)&Vth, g_Vth);
    cudaGetSymbolAddress((void**)&cth, g_cth);
    cudaGetSymbolAddress((void**)&aoh, g_aoh);
    cudaGetSymbolAddress((void**)&Fh, g_Fh);
    cudaGetSymbolAddress((void**)&Ph, g_Ph);
    cudaGetSymbolAddress((void**)&Sh, g_Sh);
    cudaGetSymbolAddress((void**)&WT, g_WT);
    cudaGetSymbolAddress((void**)&X, g_X);
    cudaGetSymbolAddress((void**)&ao, g_ao);
    cudaGetSymbolAddress((void**)&Z, g_Z);

    const size_t nMD = (size_t)Mm * Dd;
    const size_t nS  = (size_t)Bb * Hh * Ss * Ss;

    __half *wqT = WT;
    __half *wkT = WT + (size_t)Dd * Dd;
    __half *wvT = WT + (size_t)2 * Dd * Dd;
    __half *woT = WT + (size_t)3 * Dd * Dd;
    __half *w1T = WT + (size_t)4 * Dd * Dd;
    __half *w2T = w1T + (size_t)Dd * Ff;

    const long long main_elems = (long long)Mm * Dd;
    const long long attn_elems = (long long)nS;
    float* attn_ext = ((long long)out_size >= main_elems + attn_elems)
                          ? (out + main_elems) : nullptr;

    // BN=128: stage = 20480 ; 3 stages = 61440 (2 CTAs/SM -> 122880)
    const int DSZ128 = 3 * (10240 + 128 * 80);
    const int DSZ64  = 3 * (10240 + 64 * 80);
    cudaFuncSetAttribute(gemm_ps<128,0,2>, cudaFuncAttributeMaxDynamicSharedMemorySize, DSZ128);
    cudaFuncSetAttribute(gemm_ps<128,0,0>, cudaFuncAttributeMaxDynamicSharedMemorySize, DSZ128);
    cudaFuncSetAttribute(gemm_ps<128,1,2>, cudaFuncAttributeMaxDynamicSharedMemorySize, DSZ128);
    cudaFuncSetAttribute(gemm_ps<128,2,2>, cudaFuncAttributeMaxDynamicSharedMemorySize, DSZ128);
    cudaFuncSetAttribute(gemm_ps<64,3,2>,  cudaFuncAttributeMaxDynamicSharedMemorySize, DSZ64);

    dim3 tblk(32, 8);

    convert_f16<<<nMD / 1024, 256>>>(query, qh);
    convert_f16<<<nMD / 1024, 256>>>(key,   kh);
    convert_f16<<<nMD / 1024, 256>>>(value, vh);
    transpose_f16<<<dim3(Dd/32, Dd/32), tblk>>>(wq, wqT, Dd, Dd);
    transpose_f16<<<dim3(Dd/32, Dd/32), tblk>>>(wk, wkT, Dd, Dd);
    transpose_f16<<<dim3(Dd/32, Dd/32), tblk>>>(wv, wvT, Dd, Dd);
    transpose_f16<<<dim3(Dd/32, Dd/32), tblk>>>(wo, woT, Dd, Dd);
    transpose_f16<<<dim3(Ff/32, Dd/32), tblk>>>(w1, w1T, Dd, Ff);
    transpose_f16<<<dim3(Dd/32, Ff/32), tblk>>>(w2, w2T, Ff, Dd);

    // QKV projections -> fp16
    gemm_ps<128,0,2><<<dim3(Dd/128, Mm/128, 1), 256, DSZ128>>>(
        qh, Dd, 0, 0, wqT, Dd, 0, 0,
        nullptr, Qh, Dd, 0, 0, bq, Dd);
    gemm_ps<128,0,2><<<dim3(Dd/128, Mm/128, 1), 256, DSZ128>>>(
        kh, Dd, 0, 0, wkT, Dd, 0, 0,
        nullptr, Kh, Dd, 0, 0, bk, Dd);
    gemm_ps<128,0,2><<<dim3(Dd/128, Mm/128, 1), 256, DSZ128>>>(
        vh, Dd, 0, 0, wvT, Dd, 0, 0,
        nullptr, Vh, Dd, 0, 0, bv, Dd);

    // V^T per head
    vt_f16<<<dim3(Ss/32, HDIM/32, Bb*Hh), tblk>>>(Vh, Vth);

    // scores = QK^T/8 + mask -> fp16 Sh
    gemm_ps<128,2,2><<<dim3(Ss/128, Ss/128, Bb*Hh), 256, DSZ128>>>(
        Qh, Dd, (long long)Ss*Dd, HDIM,
        Kh, Dd, (long long)Ss*Dd, HDIM,
        nullptr, Sh, Ss, 16LL*Ss*Ss, (long long)Ss*Ss,
        mask, HDIM);

    // softmax -> attn_weights mirror + fp16 P
    softmax_kernel<<<Bb*Hh*Ss, 256>>>(Sh, attn_ext, Ph);

    // context = P @ V -> fp16
    gemm_ps<64,3,2><<<dim3(1, Ss/128, Bb*Hh), 256, DSZ64>>>(
        Ph, Ss, 16LL*Ss*Ss, (long long)Ss*Ss,
        Vth, Ss, 16LL*HDIM*Ss, (long long)HDIM*Ss,
        nullptr, cth, Dd, (long long)Ss*Dd, HDIM,
        nullptr, Ss);

    // O-projection -> fp32 X
    gemm_ps<128,0,0><<<dim3(Dd/128, Mm/128, 1), 256, DSZ128>>>(
        cth, Dd, 0, 0, woT, Dd, 0, 0,
        X, nullptr, Dd, 0, 0, bo, Dd);

    // Double LayerNorm -> attn_out fp32 + fp16
    ln_a_kernel<<<Mm, 256>>>(X, query, ln_mha_g, ln_mha_b,
                             ln_attn_g, ln_attn_b, ao, aoh);

    // FFN1 -> fp16 (relu)
    gemm_ps<128,1,2><<<dim3(Ff/128, Mm/128, 1), 256, DSZ128>>>(
        aoh, Dd, 0, 0, w1T, Dd, 0, 0,
        nullptr, Fh, Ff, 0, 0, b1, Dd);

    // FFN2 -> fp32 Z
    gemm_ps<128,0,0><<<dim3(Dd/128, Mm/128, 1), 256, DSZ128>>>(
        Fh, Ff, 0, 0, w2T, Ff, 0, 0,
        Z, nullptr, Dd, 0, 0, b2, Ff);

    // Final LayerNorm -> main output
    ln_b_kernel<<<Mm, 256>>>(Z, ao, ln_ffn_g, ln_ffn_b, out);
}

// round 11
// speedup vs baseline: 2.1398x; 1.0463x over previous
#include <cuda_runtime.h>
#include <cuda_fp16.h>
#include <math.h>
#include <stdint.h>

#define Bb 8
#define Ss 1024
#define Dd 1024
#define Hh 16
#define HDIM 64
#define Ff 4096
#define Mm (Bb*Ss)

// ---------------------------------------------------------------------------
// Scratch (device globals). All GEMM operands single-plane fp16.
// ---------------------------------------------------------------------------
__device__ __half g_qh [(size_t)Mm*Dd];
__device__ __half g_kh [(size_t)Mm*Dd];
__device__ __half g_vh [(size_t)Mm*Dd];
__device__ __half g_Qh [(size_t)Mm*Dd];
__device__ __half g_Kh [(size_t)Mm*Dd];
__device__ __half g_Vh [(size_t)Mm*Dd];
__device__ __half g_Vth[(size_t)Bb*Hh*HDIM*Ss];
__device__ __half g_cth[(size_t)Mm*Dd];
__device__ __half g_aoh[(size_t)Mm*Dd];
__device__ __half g_Fh [(size_t)Mm*Ff];
__device__ __half g_Sh [(size_t)Bb*Hh*Ss*Ss];      // scores fp16 (post-mask)
__device__ __half g_WT [(size_t)(4*Dd*Dd + Dd*Ff + Ff*Dd)];
__device__ float  g_X  [(size_t)Mm*Dd];
__device__ float  g_ao [(size_t)Mm*Dd];
__device__ float  g_Z  [(size_t)Mm*Dd];

// ---------------------------------------------------------------------------
// PTX helpers
// ---------------------------------------------------------------------------
__device__ __forceinline__ uint32_t smem_u32(const void* p) {
    uint32_t a;
    asm("{ .reg .u64 t; cvta.to.shared.u64 t, %1; cvt.u32.u64 %0, t; }"
        : "=r"(a) : "l"(p));
    return a;
}
__device__ __forceinline__ void ldsm4(uint32_t& r0, uint32_t& r1, uint32_t& r2,
                                      uint32_t& r3, uint32_t addr) {
    asm volatile("ldmatrix.sync.aligned.m8n8.x4.shared.b16 {%0,%1,%2,%3}, [%4];"
                 : "=r"(r0), "=r"(r1), "=r"(r2), "=r"(r3) : "r"(addr));
}
__device__ __forceinline__ void mma16816(float* d, const uint32_t* a,
                                         const uint32_t* b) {
    asm volatile(
        "mma.sync.aligned.m16n8k16.row.col.f32.f16.f16.f32 "
        "{%0,%1,%2,%3}, {%4,%5,%6,%7}, {%8,%9}, {%0,%1,%2,%3};"
        : "+f"(d[0]), "+f"(d[1]), "+f"(d[2]), "+f"(d[3])
        : "r"(a[0]), "r"(a[1]), "r"(a[2]), "r"(a[3]), "r"(b[0]), "r"(b[1]));
}
__device__ __forceinline__ void cpa16(uint32_t dst, const void* src) {
    asm volatile("cp.async.cg.shared.global [%0], [%1], 16;"
                 :: "r"(dst), "l"(src) : "memory");
}
#define CP_COMMIT() asm volatile("cp.async.commit_group;" ::: "memory")
#define CP_WAIT0()  asm volatile("cp.async.wait_group 0;" ::: "memory")
#define CP_WAIT1()  asm volatile("cp.async.wait_group 1;" ::: "memory")

__device__ __forceinline__ uint32_t packh2(float a, float b) {
    __half2 h = __floats2half2_rn(a, b);
    return *(uint32_t*)&h;
}

// ---------------------------------------------------------------------------
// GEMM: C[128 x BN] = A[128,K] @ B[BN,K]^T, fp32 accum, fp16 operands.
//   3-stage cp.async pipeline, 2 CTAs/SM. Warp grid 2(m) x 4(n).
//   EPI: 0=+bias  1=+bias,relu ; CFMT: 0 = fp32 out ; 2 = fp16 out
// ---------------------------------------------------------------------------
template<int BN, int EPI, int CFMT>
__global__ void __launch_bounds__(256, 2) gemm_ps(
    const __half* __restrict__ AH,
    long long lda,
    const __half* __restrict__ BH,
    long long ldb,
    float* __restrict__ C, __half* __restrict__ CH,
    long long ldc,
    const float* __restrict__ aux, int K)
{
    constexpr int MF = 4;
    constexpr int NF = BN / 32;
    constexpr int NBI = BN / 64;
    constexpr int ABYTES = 10240;
    constexpr int STAGE = ABYTES + BN * 80;

    extern __shared__ char dsm[];

    const int tid = threadIdx.x, lane = tid & 31, wid = tid >> 5;
    const int row0 = blockIdx.y * 128, col0 = blockIdx.x * BN;
    const int m0w = (wid >> 2) * 64, n0w = (wid & 3) * (BN / 4);

    const __half* Abh = AH + (size_t)row0 * lda;
    const __half* Bbh = BH + (size_t)col0 * ldb;

    const uint32_t sbase = smem_u32(dsm);

    float acc[MF][NF][4];
#pragma unroll
    for (int i = 0; i < MF; i++)
#pragma unroll
        for (int j = 0; j < NF; j++)
#pragma unroll
            for (int k = 0; k < 4; k++) acc[i][j][k] = 0.f;

    auto issue = [&](int st, int k0) {
        uint32_t base = sbase + st * STAGE;
#pragma unroll
        for (int i = 0; i < 2; i++) {
            int q = tid + i * 256;
            int r = q >> 2, g = q & 3;
            cpa16(base + r * 80 + g * 16, Abh + (size_t)r * lda + k0 + g * 8);
        }
#pragma unroll
        for (int i = 0; i < NBI; i++) {
            int q = tid + i * 256;
            int r = q >> 2, g = q & 3;
            cpa16(base + ABYTES + r * 80 + g * 16,
                  Bbh + (size_t)r * ldb + k0 + g * 8);
        }
        CP_COMMIT();
    };

    const int NC = K >> 5;
    issue(0, 0);
    if (NC > 1) issue(1, 32);

    for (int c = 0; c < NC; c++) {
        if (c + 1 < NC) CP_WAIT1(); else CP_WAIT0();
        __syncthreads();
        if (c + 2 < NC) issue((c + 2) % 3, (c + 2) * 32);

        const uint32_t aAh = sbase + (c % 3) * STAGE;
        const uint32_t aBh = aAh + ABYTES;
#pragma unroll
        for (int kk = 0; kk < 32; kk += 16) {
            uint32_t bh[NF][2];
#pragma unroll
            for (int np = 0; np < NF / 2; np++) {
                uint32_t bo = (uint32_t)((n0w + np * 16 + ((lane >> 4) << 3) +
                                          (lane & 7)) * 40 +
                                         kk + ((lane >> 3) & 1) * 8) * 2;
                ldsm4(bh[2 * np][0], bh[2 * np][1], bh[2 * np + 1][0],
                      bh[2 * np + 1][1], aBh + bo);
            }
#pragma unroll
            for (int mi = 0; mi < MF; mi++) {
                uint32_t ao = (uint32_t)((m0w + mi * 16 + (lane & 15)) * 40 +
                                         kk + ((lane >> 4) << 3)) * 2;
                uint32_t ah[4];
                ldsm4(ah[0], ah[1], ah[2], ah[3], aAh + ao);
#pragma unroll
                for (int ni = 0; ni < NF; ni++)
                    mma16816(acc[mi][ni], ah, bh[ni]);
            }
        }
        __syncthreads();
    }

#pragma unroll
    for (int ni = 0; ni < NF; ni++) {
        const int col = col0 + n0w + ni * 8 + (lane & 3) * 2;
        float2 e = *(const float2*)(aux + col);
#pragma unroll
        for (int mi = 0; mi < MF; mi++) {
            const int r0g = row0 + m0w + mi * 16 + (lane >> 2);
            float* a = acc[mi][ni];
            float2 v0 = make_float2(a[0] + e.x, a[1] + e.y);
            float2 v1 = make_float2(a[2] + e.x, a[3] + e.y);
            if (EPI == 1) {
                v0.x = fmaxf(v0.x, 0.f); v0.y = fmaxf(v0.y, 0.f);
                v1.x = fmaxf(v1.x, 0.f); v1.y = fmaxf(v1.y, 0.f);
            }
            if (CFMT == 0) {
                *(float2*)(C + (size_t)r0g * ldc + col) = v0;
                *(float2*)(C + (size_t)(r0g + 8) * ldc + col) = v1;
            } else {
                *(__half2*)(CH + (size_t)r0g * ldc + col) =
                    __floats2half2_rn(v0.x, v0.y);
                *(__half2*)(CH + (size_t)(r0g + 8) * ldc + col) =
                    __floats2half2_rn(v1.x, v1.y);
            }
        }
    }
}

// ---------------------------------------------------------------------------
// Flash attention: scores + online softmax + PV, one CTA = 128 q-rows of one
// (b,h). 8 warps, warp tile = 16 rows x full width (row stats warp-local).
// Writes: Sh (post-mask pre-exp scores, fp16) and cth (context, fp16).
// ---------------------------------------------------------------------------
__global__ void __launch_bounds__(256, 1) flash_attn(
    const __half* __restrict__ Qh, const __half* __restrict__ Kh,
    const __half* __restrict__ Vth, const float* __restrict__ mask,
    __half* __restrict__ Sh, __half* __restrict__ cth)
{
    constexpr int TW = 128;    // kv tile width
    constexpr int DST = 72;    // Q/K smem row stride (halves); row = 64 halves
    constexpr int VST = 136;   // V smem row stride (halves); row = 128 halves

    extern __shared__ char dsm[];
    __half* Qs  = (__half*)dsm;                                   // 18432 B
    __half* Ks0 = (__half*)(dsm + 18432);                         // 2x18432
    __half* Vs0 = (__half*)(dsm + 18432 + 2 * 18432);             // 2x17408
    float* madd = (float*)(dsm + 18432 + 2 * 18432 + 2 * 17408);  // 4096

    const int tid = threadIdx.x, lane = tid & 31, wid = tid >> 5;
    const int bh = blockIdx.y, b = bh >> 4, h = bh & 15;
    const int q0 = blockIdx.x * 128;

    const __half* Qb = Qh + (size_t)b * Ss * Dd + (size_t)h * HDIM + (size_t)q0 * Dd;
    const __half* Kb = Kh + (size_t)b * Ss * Dd + (size_t)h * HDIM;
    const __half* Vb = Vth + (size_t)bh * HDIM * Ss;
    __half* Shb = Sh + (size_t)bh * Ss * Ss + (size_t)q0 * Ss;
    __half* Cb  = cth + (size_t)b * Ss * Dd + (size_t)h * HDIM + (size_t)q0 * Dd;

    // mask -> smem additive term
    {
        float4 mv = *(const float4*)(mask + (size_t)b * Ss + tid * 4);
        madd[tid * 4 + 0] = (1.f - mv.x) * -10000.f;
        madd[tid * 4 + 1] = (1.f - mv.y) * -10000.f;
        madd[tid * 4 + 2] = (1.f - mv.z) * -10000.f;
        madd[tid * 4 + 3] = (1.f - mv.w) * -10000.f;
    }

    // Q/K rows: 64 halves = 128 B = 8 x 16B groups -> 1024 copies (4 iters)
    // V rows (64 of them): 128 halves = 256 B = 16 groups -> 1024 copies
    auto issueKV = [&](int st, int t) {
        __half* kd = Ks0 + st * (DST * 128);
        const __half* ks = Kb + (size_t)(t * TW) * Dd;
#pragma unroll
        for (int i = 0; i < 4; i++) {
            int q = tid + i * 256;
            int r = q >> 3, g = q & 7;
            cpa16(smem_u32(kd + r * DST + g * 8), ks + (size_t)r * Dd + g * 8);
        }
        __half* vd = Vs0 + st * (VST * 64);
#pragma unroll
        for (int i = 0; i < 4; i++) {
            int q = tid + i * 256;
            int r = q >> 4, g = q & 15;
            cpa16(smem_u32(vd + r * VST + g * 8),
                  Vb + (size_t)r * Ss + t * TW + g * 8);
        }
        CP_COMMIT();
    };

    // Q load (committed with KV tile 0's group)
#pragma unroll
    for (int i = 0; i < 4; i++) {
        int q = tid + i * 256;
        int r = q >> 3, g = q & 7;
        cpa16(smem_u32(Qs + r * DST + g * 8), Qb + (size_t)r * Dd + g * 8);
    }
    issueKV(0, 0);
    issueKV(1, 1);

    const int r0w = wid * 16;
    const uint32_t qbase = smem_u32(Qs);

    float m0 = -1e30f, m1 = -1e30f, l0 = 0.f, l1 = 0.f;
    float acco[8][4];
#pragma unroll
    for (int i = 0; i < 8; i++)
#pragma unroll
        for (int j = 0; j < 4; j++) acco[i][j] = 0.f;

    const int NT = Ss / TW;  // 8
    for (int t = 0; t < NT; t++) {
        if (t + 1 < NT) CP_WAIT1(); else CP_WAIT0();
        __syncthreads();

        const uint32_t kbase = smem_u32(Ks0 + (t & 1) * (DST * 128));
        const uint32_t vbase = smem_u32(Vs0 + (t & 1) * (VST * 64));

        // ---- S = Q K^T  (per warp 16x128) ----
        float accs[16][4];
#pragma unroll
        for (int i = 0; i < 16; i++)
#pragma unroll
            for (int j = 0; j < 4; j++) accs[i][j] = 0.f;

#pragma unroll
        for (int kk = 0; kk < 64; kk += 16) {
            uint32_t ah[4];
            ldsm4(ah[0], ah[1], ah[2], ah[3],
                  qbase + (uint32_t)((r0w + (lane & 15)) * DST + kk +
                                     ((lane >> 4) << 3)) * 2);
#pragma unroll
            for (int np = 0; np < 8; np++) {
                uint32_t b0, b1, b2, b3;
                ldsm4(b0, b1, b2, b3,
                      kbase + (uint32_t)((np * 16 + ((lane >> 4) << 3) +
                                          (lane & 7)) * DST + kk +
                                         ((lane >> 3) & 1) * 8) * 2);
                uint32_t bf0[2] = { b0, b1 }, bf1[2] = { b2, b3 };
                mma16816(accs[2 * np], ah, bf0);
                mma16816(accs[2 * np + 1], ah, bf1);
            }
        }

        // ---- scale + mask + row max ----
        float mx0 = -1e30f, mx1 = -1e30f;
#pragma unroll
        for (int ni = 0; ni < 16; ni++) {
            int col = t * TW + ni * 8 + (lane & 3) * 2;
            float e0 = madd[col], e1 = madd[col + 1];
            accs[ni][0] = accs[ni][0] * 0.125f + e0;
            accs[ni][1] = accs[ni][1] * 0.125f + e1;
            accs[ni][2] = accs[ni][2] * 0.125f + e0;
            accs[ni][3] = accs[ni][3] * 0.125f + e1;
            mx0 = fmaxf(mx0, fmaxf(accs[ni][0], accs[ni][1]));
            mx1 = fmaxf(mx1, fmaxf(accs[ni][2], accs[ni][3]));
        }
        mx0 = fmaxf(mx0, __shfl_xor_sync(~0u, mx0, 1));
        mx0 = fmaxf(mx0, __shfl_xor_sync(~0u, mx0, 2));
        mx1 = fmaxf(mx1, __shfl_xor_sync(~0u, mx1, 1));
        mx1 = fmaxf(mx1, __shfl_xor_sync(~0u, mx1, 2));

        // ---- store raw scores tile (fp16) ----
        {
            const int row = r0w + (lane >> 2);
#pragma unroll
            for (int ni = 0; ni < 16; ni++) {
                int col = t * TW + ni * 8 + (lane & 3) * 2;
                *(__half2*)(Shb + (size_t)row * Ss + col) =
                    __floats2half2_rn(accs[ni][0], accs[ni][1]);
                *(__half2*)(Shb + (size_t)(row + 8) * Ss + col) =
                    __floats2half2_rn(accs[ni][2], accs[ni][3]);
            }
        }

        // ---- online softmax update ----
        float mn0 = fmaxf(m0, mx0), mn1 = fmaxf(m1, mx1);
        float rs0 = __expf(m0 - mn0), rs1 = __expf(m1 - mn1);
        float s0 = 0.f, s1 = 0.f;
#pragma unroll
        for (int ni = 0; ni < 16; ni++) {
            accs[ni][0] = __expf(accs[ni][0] - mn0);
            accs[ni][1] = __expf(accs[ni][1] - mn0);
            accs[ni][2] = __expf(accs[ni][2] - mn1);
            accs[ni][3] = __expf(accs[ni][3] - mn1);
            s0 += accs[ni][0] + accs[ni][1];
            s1 += accs[ni][2] + accs[ni][3];
        }
        s0 += __shfl_xor_sync(~0u, s0, 1);
        s0 += __shfl_xor_sync(~0u, s0, 2);
        s1 += __shfl_xor_sync(~0u, s1, 1);
        s1 += __shfl_xor_sync(~0u, s1, 2);
        l0 = l0 * rs0 + s0;
        l1 = l1 * rs1 + s1;
        m0 = mn0; m1 = mn1;
#pragma unroll
        for (int no = 0; no < 8; no++) {
            acco[no][0] *= rs0; acco[no][1] *= rs0;
            acco[no][2] *= rs1; acco[no][3] *= rs1;
        }

        // ---- O += P V ----
#pragma unroll
        for (int ks = 0; ks < 8; ks++) {
            uint32_t ap[4];
            ap[0] = packh2(accs[2 * ks][0], accs[2 * ks][1]);
            ap[1] = packh2(accs[2 * ks][2], accs[2 * ks][3]);
            ap[2] = packh2(accs[2 * ks + 1][0], accs[2 * ks + 1][1]);
            ap[3] = packh2(accs[2 * ks + 1][2], accs[2 * ks + 1][3]);
#pragma unroll
            for (int np = 0; np < 4; np++) {
                uint32_t b0, b1, b2, b3;
                ldsm4(b0, b1, b2, b3,
                      vbase + (uint32_t)((np * 16 + ((lane >> 4) << 3) +
                                          (lane & 7)) * VST + ks * 16 +
                                         ((lane >> 3) & 1) * 8) * 2);
                uint32_t bf0[2] = { b0, b1 }, bf1[2] = { b2, b3 };
                mma16816(acco[2 * np], ap, bf0);
                mma16816(acco[2 * np + 1], ap, bf1);
            }
        }
        __syncthreads();
        if (t + 2 < NT) issueKV(t & 1, t + 2);
    }

    // ---- epilogue ----
    const float inv0 = 1.f / l0, inv1 = 1.f / l1;
    const int row = r0w + (lane >> 2);
#pragma unroll
    for (int no = 0; no < 8; no++) {
        int col = no * 8 + (lane & 3) * 2;
        *(__half2*)(Cb + (size_t)row * Dd + col) =
            __floats2half2_rn(acco[no][0] * inv0, acco[no][1] * inv0);
        *(__half2*)(Cb + (size_t)(row + 8) * Dd + col) =
            __floats2half2_rn(acco[no][2] * inv1, acco[no][3] * inv1);
    }
}

// ---------------------------------------------------------------------------
// Finalize: attn_weights = softmax(Sh) in fp32 (mandatory output)
// ---------------------------------------------------------------------------
__global__ void __launch_bounds__(256) finalize_kernel(
    const __half* __restrict__ S, float* __restrict__ ext)
{
    __shared__ float sbuf[8];
    const size_t row = blockIdx.x;
    const __half* p = S + row * Ss;
    const int tid = threadIdx.x;
    const int lane = tid & 31, w = tid >> 5;

    __half2 h0 = *(const __half2*)(p + tid * 4);
    __half2 h1 = *(const __half2*)(p + tid * 4 + 2);
    float2 f0 = __half22float2(h0), f1 = __half22float2(h1);
    float4 x = make_float4(f0.x, f0.y, f1.x, f1.y);
    float m = fmaxf(fmaxf(x.x, x.y), fmaxf(x.z, x.w));
#pragma unroll
    for (int o = 16; o > 0; o >>= 1) m = fmaxf(m, __shfl_xor_sync(~0u, m, o));
    if (lane == 0) sbuf[w] = m;
    __syncthreads();
    m = sbuf[0];
#pragma unroll
    for (int i = 1; i < 8; i++) m = fmaxf(m, sbuf[i]);

    float4 e;
    e.x = __expf(x.x - m); e.y = __expf(x.y - m);
    e.z = __expf(x.z - m); e.w = __expf(x.w - m);
    float s = e.x + e.y + e.z + e.w;
#pragma unroll
    for (int o = 16; o > 0; o >>= 1) s += __shfl_xor_sync(~0u, s, o);
    __syncthreads();
    if (lane == 0) sbuf[w] = s;
    __syncthreads();
    s = 0.f;
#pragma unroll
    for (int i = 0; i < 8; i++) s += sbuf[i];
    float inv = 1.0f / s;
    e.x *= inv; e.y *= inv; e.z *= inv; e.w *= inv;
    *(float4*)(ext + row * Ss + tid * 4) = e;
}

// ---------------------------------------------------------------------------
// Prologue kernels
// ---------------------------------------------------------------------------
__global__ void __launch_bounds__(256) convert_f16(
    const float* __restrict__ X, __half* __restrict__ H)
{
    size_t i = (size_t)blockIdx.x * 256 + threadIdx.x;
    float4 v = ((const float4*)X)[i];
    *(__half2*)(H + i * 4)     = __floats2half2_rn(v.x, v.y);
    *(__half2*)(H + i * 4 + 2) = __floats2half2_rn(v.z, v.w);
}

__global__ void transpose_f16(const float* __restrict__ W,
                              __half* __restrict__ TH, int R, int C)
{
    __shared__ float t[32][33];
    int c0 = blockIdx.x * 32, r0 = blockIdx.y * 32;
#pragma unroll
    for (int i = threadIdx.y; i < 32; i += 8)
        t[i][threadIdx.x] = W[(size_t)(r0 + i) * C + c0 + threadIdx.x];
    __syncthreads();
#pragma unroll
    for (int i = threadIdx.y; i < 32; i += 8)
        TH[(size_t)(c0 + i) * R + r0 + threadIdx.x] =
            __float2half_rn(t[threadIdx.x][i]);
}

__global__ void vt_f16(const __half* __restrict__ VH, __half* __restrict__ TH)
{
    __shared__ __half t[32][33];
    const int bh = blockIdx.z, b = bh >> 4, h = bh & 15;
    const int sk0 = blockIdx.x * 32, d0 = blockIdx.y * 32;
    const __half* vh = VH + (size_t)b * Ss * Dd + h * HDIM;
#pragma unroll
    for (int i = threadIdx.y; i < 32; i += 8)
        t[i][threadIdx.x] = vh[(size_t)(sk0 + i) * Dd + d0 + threadIdx.x];
    __syncthreads();
    __half* oh = TH + (size_t)bh * HDIM * Ss;
#pragma unroll
    for (int i = threadIdx.y; i < 32; i += 8)
        oh[(size_t)(d0 + i) * Ss + sk0 + threadIdx.x] = t[threadIdx.x][i];
}

// ---------------------------------------------------------------------------
// LayerNorm kernels
// ---------------------------------------------------------------------------
__device__ __forceinline__ float block_sum(float v, float* sbuf) {
    const int lane = threadIdx.x & 31, w = threadIdx.x >> 5;
#pragma unroll
    for (int o = 16; o > 0; o >>= 1) v += __shfl_xor_sync(~0u, v, o);
    __syncthreads();
    if (lane == 0) sbuf[w] = v;
    __syncthreads();
    float s = 0.f;
#pragma unroll
    for (int i = 0; i < 8; i++) s += sbuf[i];
    return s;
}

__global__ void __launch_bounds__(256) ln_a_kernel(
    const float* __restrict__ X, const float* __restrict__ q,
    const float* __restrict__ g1, const float* __restrict__ b1,
    const float* __restrict__ g2, const float* __restrict__ b2,
    float* __restrict__ out, __half* __restrict__ OH)
{
    __shared__ float sbuf[8];
    const size_t row = blockIdx.x;
    const int col = threadIdx.x * 4;
    float4 xv = *(const float4*)(X + row * Dd + col);
    float4 qv = *(const float4*)(q + row * Dd + col);
    float t[4] = { xv.x + qv.x, xv.y + qv.y, xv.z + qv.z, xv.w + qv.w };

    float mu = block_sum(t[0] + t[1] + t[2] + t[3], sbuf) * (1.0f / Dd);
    float ss = 0.f;
#pragma unroll
    for (int i = 0; i < 4; i++) { float d = t[i] - mu; ss += d * d; }
    float var = block_sum(ss, sbuf) * (1.0f / Dd);
    float inv = rsqrtf(var + 1e-8f);

    float4 g = *(const float4*)(g1 + col);
    float4 be = *(const float4*)(b1 + col);
    float qarr[4] = { qv.x, qv.y, qv.z, qv.w };
    float garr[4] = { g.x, g.y, g.z, g.w };
    float barr[4] = { be.x, be.y, be.z, be.w };
    float t2[4];
#pragma unroll
    for (int i = 0; i < 4; i++)
        t2[i] = qarr[i] + (t[i] - mu) * inv * garr[i] + barr[i];

    float mu2 = block_sum(t2[0] + t2[1] + t2[2] + t2[3], sbuf) * (1.0f / Dd);
    float ss2 = 0.f;
#pragma unroll
    for (int i = 0; i < 4; i++) { float d = t2[i] - mu2; ss2 += d * d; }
    float var2 = block_sum(ss2, sbuf) * (1.0f / Dd);
    float inv2 = rsqrtf(var2 + 1e-6f);

    g = *(const float4*)(g2 + col);
    be = *(const float4*)(b2 + col);
    float4 o;
    o.x = (t2[0] - mu2) * inv2 * g.x + be.x;
    o.y = (t2[1] - mu2) * inv2 * g.y + be.y;
    o.z = (t2[2] - mu2) * inv2 * g.z + be.z;
    o.w = (t2[3] - mu2) * inv2 * g.w + be.w;
    *(float4*)(out + row * Dd + col) = o;
    *(__half2*)(OH + row * Dd + col)     = __floats2half2_rn(o.x, o.y);
    *(__half2*)(OH + row * Dd + col + 2) = __floats2half2_rn(o.z, o.w);
}

__global__ void __launch_bounds__(256) ln_b_kernel(
    const float* __restrict__ Z, const float* __restrict__ res,
    const float* __restrict__ g1, const float* __restrict__ b1,
    float* __restrict__ out)
{
    __shared__ float sbuf[8];
    const size_t row = blockIdx.x;
    const int col = threadIdx.x * 4;
    float4 zv = *(const float4*)(Z + row * Dd + col);
    float4 rv = *(const float4*)(res + row * Dd + col);
    float t[4] = { zv.x + rv.x, zv.y + rv.y, zv.z + rv.z, zv.w + rv.w };

    float mu = block_sum(t[0] + t[1] + t[2] + t[3], sbuf) * (1.0f / Dd);
    float ss = 0.f;
#pragma unroll
    for (int i = 0; i < 4; i++) { float d = t[i] - mu; ss += d * d; }
    float var = block_sum(ss, sbuf) * (1.0f / Dd);
    float inv = rsqrtf(var + 1e-6f);

    float4 g = *(const float4*)(g1 + col);
    float4 be = *(const float4*)(b1 + col);
    float4 o;
    o.x = (t[0] - mu) * inv * g.x + be.x;
    o.y = (t[1] - mu) * inv * g.y + be.y;
    o.z = (t[2] - mu) * inv * g.z + be.z;
    o.w = (t[3] - mu) * inv * g.w + be.w;
    *(float4*)(out + row * Dd + col) = o;
}

// ---------------------------------------------------------------------------
// kernel_launch
// ---------------------------------------------------------------------------
extern "C" void kernel_launch(void* const* d_in, const int* in_sizes, int n_in,
                              void* d_out, int out_size)
{
    const float* query = (const float*)d_in[0];
    const float* key   = (const float*)d_in[1];
    const float* value = (const float*)d_in[2];
    const float* mask  = (const float*)d_in[3];
    const float* wq = (const float*)d_in[4];
    const float* bq = (const float*)d_in[5];
    const float* wk = (const float*)d_in[6];
    const float* bk = (const float*)d_in[7];
    const float* wv = (const float*)d_in[8];
    const float* bv = (const float*)d_in[9];
    const float* wo = (const float*)d_in[10];
    const float* bo = (const float*)d_in[11];
    const float* ln_mha_g = (const float*)d_in[12];
    const float* ln_mha_b = (const float*)d_in[13];
    const float* w1 = (const float*)d_in[14];
    const float* b1 = (const float*)d_in[15];
    const float* w2 = (const float*)d_in[16];
    const float* b2 = (const float*)d_in[17];
    const float* ln_attn_g = (const float*)d_in[18];
    const float* ln_attn_b = (const float*)d_in[19];
    const float* ln_ffn_g = (const float*)d_in[20];
    const float* ln_ffn_b = (const float*)d_in[21];
    (void)in_sizes; (void)n_in;

    float* out = (float*)d_out;

    __half *qh, *kh, *vh, *Qh, *Kh, *Vh, *Vth, *cth, *aoh, *Fh, *Sh, *WT;
    float *X, *ao, *Z;
    cudaGetSymbolAddress((void**)&qh, g_qh);
    cudaGetSymbolAddress((void**)&kh, g_kh);
    cudaGetSymbolAddress((void**)&vh, g_vh);
    cudaGetSymbolAddress((void**)&Qh, g_Qh);
    cudaGetSymbolAddress((void**)&Kh, g_Kh);
    cudaGetSymbolAddress((void**)&Vh, g_Vh);
    cudaGetSymbolAddress((void**)&Vth, g_Vth);
    cudaGetSymbolAddress((void**)&cth, g_cth);
    cudaGetSymbolAddress((void**)&aoh, g_aoh);
    cudaGetSymbolAddress((void**)&Fh, g_Fh);
    cudaGetSymbolAddress((void**)&Sh, g_Sh);
    cudaGetSymbolAddress((void**)&WT, g_WT);
    cudaGetSymbolAddress((void**)&X, g_X);
    cudaGetSymbolAddress((void**)&ao, g_ao);
    cudaGetSymbolAddress((void**)&Z, g_Z);

    const size_t nMD = (size_t)Mm * Dd;
    const size_t nS  = (size_t)Bb * Hh * Ss * Ss;

    __half *wqT = WT;
    __half *wkT = WT + (size_t)Dd * Dd;
    __half *wvT = WT + (size_t)2 * Dd * Dd;
    __half *woT = WT + (size_t)3 * Dd * Dd;
    __half *w1T = WT + (size_t)4 * Dd * Dd;
    __half *w2T = w1T + (size_t)Dd * Ff;

    const long long main_elems = (long long)Mm * Dd;
    const long long attn_elems = (long long)nS;
    float* attn_ext = ((long long)out_size >= main_elems + attn_elems)
                          ? (out + main_elems) : nullptr;

    const int DSZ128 = 3 * (10240 + 128 * 80);
    const int FSZ = 18432 + 2 * 18432 + 2 * 17408 + 4096;  // 94208
    cudaFuncSetAttribute(gemm_ps<128,0,2>, cudaFuncAttributeMaxDynamicSharedMemorySize, DSZ128);
    cudaFuncSetAttribute(gemm_ps<128,0,0>, cudaFuncAttributeMaxDynamicSharedMemorySize, DSZ128);
    cudaFuncSetAttribute(gemm_ps<128,1,2>, cudaFuncAttributeMaxDynamicSharedMemorySize, DSZ128);
    cudaFuncSetAttribute(flash_attn, cudaFuncAttributeMaxDynamicSharedMemorySize, FSZ);

    dim3 tblk(32, 8);

    convert_f16<<<nMD / 1024, 256>>>(query, qh);
    convert_f16<<<nMD / 1024, 256>>>(key,   kh);
    convert_f16<<<nMD / 1024, 256>>>(value, vh);
    transpose_f16<<<dim3(Dd/32, Dd/32), tblk>>>(wq, wqT, Dd, Dd);
    transpose_f16<<<dim3(Dd/32, Dd/32), tblk>>>(wk, wkT, Dd, Dd);
    transpose_f16<<<dim3(Dd/32, Dd/32), tblk>>>(wv, wvT, Dd, Dd);
    transpose_f16<<<dim3(Dd/32, Dd/32), tblk>>>(wo, woT, Dd, Dd);
    transpose_f16<<<dim3(Ff/32, Dd/32), tblk>>>(w1, w1T, Dd, Ff);
    transpose_f16<<<dim3(Dd/32, Ff/32), tblk>>>(w2, w2T, Ff, Dd);

    // QKV projections -> fp16
    gemm_ps<128,0,2><<<dim3(Dd/128, Mm/128), 256, DSZ128>>>(
        qh, Dd, wqT, Dd, nullptr, Qh, Dd, bq, Dd);
    gemm_ps<128,0,2><<<dim3(Dd/128, Mm/128), 256, DSZ128>>>(
        kh, Dd, wkT, Dd, nullptr, Kh, Dd, bk, Dd);
    gemm_ps<128,0,2><<<dim3(Dd/128, Mm/128), 256, DSZ128>>>(
        vh, Dd, wvT, Dd, nullptr, Vh, Dd, bv, Dd);

    // V^T per head
    vt_f16<<<dim3(Ss/32, HDIM/32, Bb*Hh), tblk>>>(Vh, Vth);

    // Fused attention: scores + online softmax + PV
    flash_attn<<<dim3(Ss/128, Bb*Hh), 256, FSZ>>>(Qh, Kh, Vth, mask, Sh, cth);

    // attn_weights output (fp32 softmax of stored scores)
    if (attn_ext)
        finalize_kernel<<<Bb*Hh*Ss, 256>>>(Sh, attn_ext);

    // O-projection -> fp32 X
    gemm_ps<128,0,0><<<dim3(Dd/128, Mm/128), 256, DSZ128>>>(
        cth, Dd, woT, Dd, X, nullptr, Dd, bo, Dd);

    // Double LayerNorm -> attn_out fp32 + fp16
    ln_a_kernel<<<Mm, 256>>>(X, query, ln_mha_g, ln_mha_b,
                             ln_attn_g, ln_attn_b, ao, aoh);

    // FFN1 -> fp16 (relu)
    gemm_ps<128,1,2><<<dim3(Ff/128, Mm/128), 256, DSZ128>>>(
        aoh, Dd, w1T, Dd, nullptr, Fh, Ff, b1, Dd);

    // FFN2 -> fp32 Z
    gemm_ps<128,0,0><<<dim3(Dd/128, Mm/128), 256, DSZ128>>>(
        Fh, Ff, w2T, Ff, Z, nullptr, Dd, b2, Ff);

    // Final LayerNorm -> main output
    ln_b_kernel<<<Mm, 256>>>(Z, ao, ln_ffn_g, ln_ffn_b, out);
}